// round 1
// baseline (speedup 1.0000x reference)
#include <cuda_runtime.h>
#include <math.h>

#define NRES 512
#define NH   12
#define HD   16
#define CS_  1024
#define CZ_  128
#define PQ_  4
#define PV_  8
#define DCAT 2112
#define INF_ 100000.0f

// ---------------- scratch ----------------
static constexpr size_t OFF_Q    = 0;                       // 512*192 (q proj, [n][h*16+d])
static constexpr size_t OFF_KV   = OFF_Q    + 512*192;      // 512*384 raw kv proj
static constexpr size_t OFF_QPR  = OFF_KV   + 512*384;      // 512*144 raw q-pts proj
static constexpr size_t OFF_KVPR = OFF_QPR  + 512*144;      // 512*432 raw kv-pts proj
static constexpr size_t OFF_KT   = OFF_KVPR + 512*432;      // [h][j][16]
static constexpr size_t OFF_V    = OFF_KT   + 512*192;      // [j][h][16]
static constexpr size_t OFF_QPTS = OFF_V    + 512*192;      // [n][h][12]
static constexpr size_t OFF_KPTS = OFF_QPTS + 512*144;      // [h][j][12]
static constexpr size_t OFF_VPTS = OFF_KPTS + 512*144;      // [j][h][24]
static constexpr size_t OFF_B    = OFF_VPTS + 512*288;      // [i][h][j]
static constexpr size_t OFF_A    = OFF_B    + (size_t)512*12*512; // [i][h][j]
static constexpr size_t OFF_CAT  = OFF_A    + (size_t)512*12*512; // [n][2112]
static constexpr size_t SCRATCH_TOTAL = OFF_CAT + (size_t)512*2112;

__device__ float g_scratch[SCRATCH_TOTAL];

// ---------------- generic tiled fp32 GEMM: C[M,N] = A[M,K] @ W[K,N] + bias ----------------
#define BM 64
#define BN 64
#define BKK 16

__global__ void gemm_rm(const float* __restrict__ A, const float* __restrict__ W,
                        const float* __restrict__ bias, float* __restrict__ C,
                        int M, int K, int Nout) {
    __shared__ float As[BKK][BM + 1];
    __shared__ float Ws[BKK][BN];
    int tid = threadIdx.x;            // 256
    int tx = tid & 15, ty = tid >> 4;
    int m0 = blockIdx.y * BM, n0 = blockIdx.x * BN;
    float acc[4][4] = {};
    for (int k0 = 0; k0 < K; k0 += BKK) {
        #pragma unroll
        for (int l = 0; l < 4; l++) {
            int idx = tid + l * 256;
            int m = idx >> 4, kk = idx & 15;
            As[kk][m] = A[(size_t)(m0 + m) * K + k0 + kk];
        }
        #pragma unroll
        for (int l = 0; l < 4; l++) {
            int idx = tid + l * 256;
            int kk = idx >> 6, n = idx & 63;
            Ws[kk][n] = (n0 + n < Nout) ? W[(size_t)(k0 + kk) * Nout + n0 + n] : 0.f;
        }
        __syncthreads();
        #pragma unroll
        for (int kk = 0; kk < BKK; kk++) {
            float af[4], bf[4];
            #pragma unroll
            for (int u = 0; u < 4; u++) af[u] = As[kk][ty * 4 + u];
            #pragma unroll
            for (int u = 0; u < 4; u++) bf[u] = Ws[kk][tx * 4 + u];
            #pragma unroll
            for (int u = 0; u < 4; u++)
                #pragma unroll
                for (int vv = 0; vv < 4; vv++)
                    acc[u][vv] += af[u] * bf[vv];
        }
        __syncthreads();
    }
    #pragma unroll
    for (int u = 0; u < 4; u++) {
        int m = m0 + ty * 4 + u;
        #pragma unroll
        for (int vv = 0; vv < 4; vv++) {
            int n = n0 + tx * 4 + vv;
            if (n < Nout) C[(size_t)m * Nout + n] = acc[u][vv] + bias[n];
        }
    }
}

// ---------------- repack k/v + rotate points ----------------
__global__ void pointify(const float* __restrict__ kvraw,
                         const float* __restrict__ qpraw,
                         const float* __restrict__ kvpraw,
                         const float* __restrict__ rot,
                         const float* __restrict__ trans,
                         float* __restrict__ kT, float* __restrict__ v,
                         float* __restrict__ qpts, float* __restrict__ kptsT,
                         float* __restrict__ vpts) {
    int n = blockIdx.x, t = threadIdx.x;   // 256 threads
    __shared__ float Rs[9], ts[3];
    if (t < 9) Rs[t] = rot[n * 9 + t];
    if (t < 3) ts[t] = trans[n * 3 + t];
    __syncthreads();
    if (t < 192) {
        int hh = t >> 4, d = t & 15;
        kT[((size_t)hh * 512 + n) * 16 + d] = kvraw[(size_t)n * 384 + hh * 32 + d];
        v[(size_t)n * 192 + t]              = kvraw[(size_t)n * 384 + hh * 32 + 16 + d];
    }
    if (t < 48) {   // q points
        float x  = qpraw[n * 144 + t];
        float y  = qpraw[n * 144 + 48 + t];
        float zc = qpraw[n * 144 + 96 + t];
        float gx = Rs[0] * x + Rs[1] * y + Rs[2] * zc + ts[0];
        float gy = Rs[3] * x + Rs[4] * y + Rs[5] * zc + ts[1];
        float gz = Rs[6] * x + Rs[7] * y + Rs[8] * zc + ts[2];
        int hh = t >> 2, p = t & 3;
        float* dst = qpts + ((size_t)n * 12 + hh) * 12 + p * 3;
        dst[0] = gx; dst[1] = gy; dst[2] = gz;
    }
    if (t >= 64 && t < 208) {  // kv points (144)
        int pf = t - 64;
        float x  = kvpraw[n * 432 + pf];
        float y  = kvpraw[n * 432 + 144 + pf];
        float zc = kvpraw[n * 432 + 288 + pf];
        float gx = Rs[0] * x + Rs[1] * y + Rs[2] * zc + ts[0];
        float gy = Rs[3] * x + Rs[4] * y + Rs[5] * zc + ts[1];
        float gz = Rs[6] * x + Rs[7] * y + Rs[8] * zc + ts[2];
        int hh = pf / 12, pp = pf % 12;
        if (pp < 4) {
            float* dst = kptsT + ((size_t)hh * 512 + n) * 12 + pp * 3;
            dst[0] = gx; dst[1] = gy; dst[2] = gz;
        } else {
            float* dst = vpts + (size_t)n * 288 + hh * 24 + (pp - 4) * 3;
            dst[0] = gx; dst[1] = gy; dst[2] = gz;
        }
    }
}

// ---------------- b[i][h][j] = z[i,j,:] @ Wb[:,h] + bb[h] ----------------
__global__ void bproj(const float* __restrict__ z,
                      const float* __restrict__ Wb,
                      const float* __restrict__ bb,
                      float* __restrict__ bmat) {
    __shared__ float Wb_s[12 * 128];
    __shared__ float bb_s[12];
    int tid = threadIdx.x;     // 128
    for (int idx = tid; idx < 1536; idx += 128) {
        int hh = idx >> 7, k = idx & 127;
        Wb_s[hh * 128 + k] = Wb[k * 12 + hh];
    }
    if (tid < 12) bb_s[tid] = bb[tid];
    __syncthreads();
    int warp = tid >> 5, lane = tid & 31;
    int row = blockIdx.x * 4 + warp;          // = i*512 + j
    const float* zr = z + (size_t)row * 128;
    float z0 = zr[lane], z1 = zr[lane + 32], z2 = zr[lane + 64], z3 = zr[lane + 96];
    float acc[12];
    #pragma unroll
    for (int hh = 0; hh < 12; hh++) {
        const float* w = Wb_s + hh * 128 + lane;
        acc[hh] = z0 * w[0] + z1 * w[32] + z2 * w[64] + z3 * w[96];
    }
    #pragma unroll
    for (int off = 16; off > 0; off >>= 1)
        #pragma unroll
        for (int hh = 0; hh < 12; hh++)
            acc[hh] += __shfl_xor_sync(0xffffffffu, acc[hh], off);
    int i = row >> 9, j = row & 511;
    #pragma unroll
    for (int hh = 0; hh < 12; hh++)
        if (lane == hh)
            bmat[((size_t)i * 12 + hh) * 512 + j] = acc[hh] + bb_s[hh];
}

// ---------------- logits + softmax per (i,h) ----------------
__global__ void logits_softmax(const float* __restrict__ q,
                               const float* __restrict__ kT,
                               const float* __restrict__ qpts,
                               const float* __restrict__ kptsT,
                               const float* __restrict__ bmat,
                               const float* __restrict__ mask,
                               const float* __restrict__ head_w,
                               float* __restrict__ a) {
    int i = blockIdx.x, h = blockIdx.y;
    int tid = threadIdx.x;    // 256
    __shared__ float q_s[16], qp_s[12], lg[512], red[256];
    __shared__ float s_hw, s_mi;
    if (tid < 16) q_s[tid] = q[(size_t)i * 192 + h * 16 + tid];
    if (tid < 12) qp_s[tid] = qpts[((size_t)i * 12 + h) * 12 + tid];
    if (tid == 0) {
        float w = head_w[h];
        float sp = (w > 20.f) ? w : log1pf(expf(w));        // softplus
        s_hw = sp * 0.13608276348795434f;                   // sqrt(1/54)
        s_mi = mask[i];
    }
    __syncthreads();
    const float c_qk = 0.14433756729740643f;  // sqrt(1/48)
    const float c_b  = 0.5773502691896258f;   // sqrt(1/3)
    float hw = s_hw, mi = s_mi;
    #pragma unroll
    for (int r = 0; r < 2; r++) {
        int j = tid + r * 256;
        const float* kp = kT + ((size_t)h * 512 + j) * 16;
        float qk = 0.f;
        #pragma unroll
        for (int d = 0; d < 16; d++) qk += q_s[d] * kp[d];
        const float* kq = kptsT + ((size_t)h * 512 + j) * 12;
        float pt = 0.f;
        #pragma unroll
        for (int u = 0; u < 12; u++) { float dd = qp_s[u] - kq[u]; pt += dd * dd; }
        lg[j] = qk * c_qk + c_b * bmat[((size_t)i * 12 + h) * 512 + j]
                - 0.5f * hw * pt + INF_ * (mi * mask[j] - 1.f);
    }
    __syncthreads();
    red[tid] = fmaxf(lg[tid], lg[tid + 256]);
    __syncthreads();
    for (int s = 128; s > 0; s >>= 1) {
        if (tid < s) red[tid] = fmaxf(red[tid], red[tid + s]);
        __syncthreads();
    }
    float mx = red[0];
    __syncthreads();
    float e0 = expf(lg[tid] - mx), e1 = expf(lg[tid + 256] - mx);
    lg[tid] = e0; lg[tid + 256] = e1;
    red[tid] = e0 + e1;
    __syncthreads();
    for (int s = 128; s > 0; s >>= 1) {
        if (tid < s) red[tid] += red[tid + s];
        __syncthreads();
    }
    float inv = 1.f / red[0];
    float* arow = a + ((size_t)i * 12 + h) * 512;
    arow[tid] = lg[tid] * inv;
    arow[tid + 256] = lg[tid + 256] * inv;
}

// ---------------- o = a@v ; o_pt = a@v_pts (+ inverse frame + norm) ----------------
__global__ void att_out(const float* __restrict__ a,
                        const float* __restrict__ v,
                        const float* __restrict__ vpts,
                        const float* __restrict__ rot,
                        const float* __restrict__ trans,
                        float* __restrict__ cat) {
    int i = blockIdx.x;
    int t = threadIdx.x;    // 480
    __shared__ float a_s[12 * 64];
    __shared__ float opts[288];
    __shared__ float Rs[9], ts[3];
    if (t < 9) Rs[t] = rot[i * 9 + t];
    if (t < 3) ts[t] = trans[i * 3 + t];
    float acc = 0.f;
    int h = (t < 192) ? (t >> 4) : ((t - 192) / 24);
    const float* src = (t < 192) ? (v + t) : (vpts + (t - 192));
    int stride = (t < 192) ? 192 : 288;
    for (int j0 = 0; j0 < 512; j0 += 64) {
        for (int idx = t; idx < 768; idx += 480) {
            int hh = idx >> 6, jj = idx & 63;
            a_s[idx] = a[((size_t)i * 12 + hh) * 512 + j0 + jj];
        }
        __syncthreads();
        const float* as = a_s + h * 64;
        const float* sp = src + (size_t)j0 * stride;
        #pragma unroll 8
        for (int jj = 0; jj < 64; jj++)
            acc += as[jj] * sp[(size_t)jj * stride];
        __syncthreads();
    }
    if (t >= 192) opts[t - 192] = acc;
    __syncthreads();
    float* crow = cat + (size_t)i * 2112;
    if (t < 192) crow[t] = acc;
    if (t < 96) {
        int hh = t >> 3, p = t & 7;
        int base = hh * 24 + p * 3;
        float gx = opts[base]     - ts[0];
        float gy = opts[base + 1] - ts[1];
        float gz = opts[base + 2] - ts[2];
        float lx = Rs[0] * gx + Rs[3] * gy + Rs[6] * gz;   // R^T v
        float ly = Rs[1] * gx + Rs[4] * gy + Rs[7] * gz;
        float lz = Rs[2] * gx + Rs[5] * gy + Rs[8] * gz;
        crow[192 + t] = lx;
        crow[288 + t] = ly;
        crow[384 + t] = lz;
        crow[480 + t] = sqrtf(lx * lx + ly * ly + lz * lz + 1e-8f);
    }
}

// ---------------- o_pair[i,h,c] = sum_j a[i,h,j] * z[i,j,c] ----------------
__global__ void opair(const float* __restrict__ a,
                      const float* __restrict__ z,
                      float* __restrict__ cat) {
    int i = blockIdx.x;
    int c = threadIdx.x;   // 128
    __shared__ float a_s[768];
    float acc[12] = {};
    for (int j0 = 0; j0 < 512; j0 += 64) {
        for (int idx = c; idx < 768; idx += 128) {
            int hh = idx >> 6, jj = idx & 63;
            a_s[idx] = a[((size_t)i * 12 + hh) * 512 + j0 + jj];
        }
        __syncthreads();
        const float* zp = z + ((size_t)i * 512 + j0) * 128 + c;
        #pragma unroll 4
        for (int jj = 0; jj < 64; jj++) {
            float zv = zp[(size_t)jj * 128];
            #pragma unroll
            for (int hh = 0; hh < 12; hh++)
                acc[hh] += a_s[hh * 64 + jj] * zv;
        }
        __syncthreads();
    }
    float* crow = cat + (size_t)i * 2112 + 576;
    #pragma unroll
    for (int hh = 0; hh < 12; hh++)
        crow[hh * 128 + c] = acc[hh];
}

// ---------------- launch ----------------
extern "C" void kernel_launch(void* const* d_in, const int* in_sizes, int n_in,
                              void* d_out, int out_size) {
    const float* s      = (const float*)d_in[0];
    const float* z      = (const float*)d_in[1];
    const float* rot    = (const float*)d_in[2];
    const float* trans  = (const float*)d_in[3];
    const float* mask   = (const float*)d_in[4];
    const float* Wq     = (const float*)d_in[5];
    const float* bq     = (const float*)d_in[6];
    const float* Wkv    = (const float*)d_in[7];
    const float* bkv    = (const float*)d_in[8];
    const float* Wqp    = (const float*)d_in[9];
    const float* bqp    = (const float*)d_in[10];
    const float* Wkvp   = (const float*)d_in[11];
    const float* bkvp   = (const float*)d_in[12];
    const float* Wb     = (const float*)d_in[13];
    const float* bb     = (const float*)d_in[14];
    const float* head_w = (const float*)d_in[15];
    const float* Wout   = (const float*)d_in[16];
    const float* bout   = (const float*)d_in[17];
    float* out = (float*)d_out;

    float* base = nullptr;
    cudaGetSymbolAddress((void**)&base, g_scratch);
    float* q    = base + OFF_Q;
    float* kv   = base + OFF_KV;
    float* qpr  = base + OFF_QPR;
    float* kvpr = base + OFF_KVPR;
    float* kT   = base + OFF_KT;
    float* v    = base + OFF_V;
    float* qpts = base + OFF_QPTS;
    float* kpts = base + OFF_KPTS;
    float* vpts = base + OFF_VPTS;
    float* bmat = base + OFF_B;
    float* amat = base + OFF_A;
    float* cat  = base + OFF_CAT;

    gemm_rm<<<dim3(3, 8), 256>>>(s, Wq,   bq,   q,    512, 1024, 192);
    gemm_rm<<<dim3(6, 8), 256>>>(s, Wkv,  bkv,  kv,   512, 1024, 384);
    gemm_rm<<<dim3(3, 8), 256>>>(s, Wqp,  bqp,  qpr,  512, 1024, 144);
    gemm_rm<<<dim3(7, 8), 256>>>(s, Wkvp, bkvp, kvpr, 512, 1024, 432);
    pointify<<<512, 256>>>(kv, qpr, kvpr, rot, trans, kT, v, qpts, kpts, vpts);
    bproj<<<65536, 128>>>(z, Wb, bb, bmat);
    logits_softmax<<<dim3(512, 12), 256>>>(q, kT, qpts, kpts, bmat, mask, head_w, amat);
    att_out<<<512, 480>>>(amat, v, vpts, rot, trans, cat);
    opair<<<512, 128>>>(amat, z, cat);
    gemm_rm<<<dim3(16, 8), 256>>>(cat, Wout, bout, out, 512, 2112, 1024);
}

// round 2
// speedup vs baseline: 1.4079x; 1.4079x over previous
#include <cuda_runtime.h>
#include <math.h>

#define INF_ 100000.0f

// ---------------- scratch ----------------
static constexpr size_t OFF_Q    = 0;                       // 512*192 (q proj, [n][h*16+d])
static constexpr size_t OFF_KV   = OFF_Q    + 512*192;      // 512*384 raw kv proj
static constexpr size_t OFF_QPR  = OFF_KV   + 512*384;      // 512*144 raw q-pts proj
static constexpr size_t OFF_KVPR = OFF_QPR  + 512*144;      // 512*432 raw kv-pts proj
static constexpr size_t OFF_KT   = OFF_KVPR + 512*432;      // [h][j][16]
static constexpr size_t OFF_V    = OFF_KT   + 512*192;      // [j][h][16]
static constexpr size_t OFF_QPTS = OFF_V    + 512*192;      // [n][h][12]
static constexpr size_t OFF_KPTS = OFF_QPTS + 512*144;      // [h][j][12]
static constexpr size_t OFF_VPTS = OFF_KPTS + 512*144;      // [j][h][24]
static constexpr size_t OFF_B    = OFF_VPTS + 512*288;      // [i][h][j]
static constexpr size_t OFF_A    = OFF_B    + (size_t)512*12*512; // [i][h][j]
static constexpr size_t OFF_CAT  = OFF_A    + (size_t)512*12*512; // [n][2112]
static constexpr size_t SCRATCH_TOTAL = OFF_CAT + (size_t)512*2112;

__device__ __align__(256) float g_scratch[SCRATCH_TOTAL];

// ---------------- 64x64x16 double-buffered fp32 GEMM body ----------------
// C[M,Nout] = A[M,K] @ W[K,Nout] + bias. M%64==0, K%16==0, Nout%4==0.
__device__ __forceinline__ void gemm64_body(const float* __restrict__ A,
                                            const float* __restrict__ W,
                                            const float* __restrict__ bias,
                                            float* __restrict__ C,
                                            int K, int Nout, int m0, int n0)
{
    __shared__ __align__(16) float As[2][16][68];   // [kk][m], padded
    __shared__ __align__(16) float Ws[2][16][64];   // [kk][n]
    int tid = threadIdx.x;                 // 256
    int tx = tid & 15, ty = tid >> 4;
    int am = tid >> 2, ak = (tid & 3) << 2;
    int wk = tid >> 4, wn = (tid & 15) << 2;
    const float* Aptr = A + (size_t)(m0 + am) * K + ak;
    bool wval = (n0 + wn) < Nout;
    const float* Wptr = W + (size_t)wk * Nout + n0 + wn;

    float4 a0 = *(const float4*)Aptr;
    float4 w0 = wval ? *(const float4*)Wptr : make_float4(0.f, 0.f, 0.f, 0.f);
    As[0][ak + 0][am] = a0.x; As[0][ak + 1][am] = a0.y;
    As[0][ak + 2][am] = a0.z; As[0][ak + 3][am] = a0.w;
    *(float4*)&Ws[0][wk][wn] = w0;
    __syncthreads();

    float acc[4][4] = {};
    int buf = 0;
    int ntiles = K >> 4;
    for (int t = 0; t < ntiles; t++) {
        float4 aN, wN;
        bool more = (t + 1 < ntiles);
        if (more) {
            aN = *(const float4*)(Aptr + (size_t)(t + 1) * 16);
            wN = wval ? *(const float4*)(Wptr + (size_t)(t + 1) * 16 * Nout)
                      : make_float4(0.f, 0.f, 0.f, 0.f);
        }
        #pragma unroll
        for (int kk = 0; kk < 16; kk++) {
            float4 af = *(const float4*)&As[buf][kk][ty << 2];
            float4 bf = *(const float4*)&Ws[buf][kk][tx << 2];
            acc[0][0] += af.x * bf.x; acc[0][1] += af.x * bf.y;
            acc[0][2] += af.x * bf.z; acc[0][3] += af.x * bf.w;
            acc[1][0] += af.y * bf.x; acc[1][1] += af.y * bf.y;
            acc[1][2] += af.y * bf.z; acc[1][3] += af.y * bf.w;
            acc[2][0] += af.z * bf.x; acc[2][1] += af.z * bf.y;
            acc[2][2] += af.z * bf.z; acc[2][3] += af.z * bf.w;
            acc[3][0] += af.w * bf.x; acc[3][1] += af.w * bf.y;
            acc[3][2] += af.w * bf.z; acc[3][3] += af.w * bf.w;
        }
        if (more) {
            int nb = buf ^ 1;
            As[nb][ak + 0][am] = aN.x; As[nb][ak + 1][am] = aN.y;
            As[nb][ak + 2][am] = aN.z; As[nb][ak + 3][am] = aN.w;
            *(float4*)&Ws[nb][wk][wn] = wN;
            __syncthreads();
            buf = nb;
        }
    }
    if (wval) {
        float4 bv = *(const float4*)&bias[n0 + (tx << 2)];
        #pragma unroll
        for (int u = 0; u < 4; u++) {
            float4 o;
            o.x = acc[u][0] + bv.x; o.y = acc[u][1] + bv.y;
            o.z = acc[u][2] + bv.z; o.w = acc[u][3] + bv.w;
            *(float4*)&C[(size_t)(m0 + (ty << 2) + u) * Nout + n0 + (tx << 2)] = o;
        }
    }
}

struct Proj4 {
    const float* W[4];
    const float* b[4];
    float* C[4];
    int Nout[4];
};

__global__ void proj_gemm(const float* __restrict__ s, Proj4 p) {
    int g = blockIdx.z;
    int Nout = p.Nout[g];
    int n0 = blockIdx.x * 64;
    if (n0 >= Nout) return;
    gemm64_body(s, p.W[g], p.b[g], p.C[g], 1024, Nout, blockIdx.y * 64, n0);
}

__global__ void gemm_one(const float* __restrict__ A, const float* __restrict__ W,
                         const float* __restrict__ bias, float* __restrict__ C,
                         int K, int Nout) {
    gemm64_body(A, W, bias, C, K, Nout, blockIdx.y * 64, blockIdx.x * 64);
}

// ---------------- repack k/v + rotate points ----------------
__global__ void pointify(const float* __restrict__ kvraw,
                         const float* __restrict__ qpraw,
                         const float* __restrict__ kvpraw,
                         const float* __restrict__ rot,
                         const float* __restrict__ trans,
                         float* __restrict__ kT, float* __restrict__ v,
                         float* __restrict__ qpts, float* __restrict__ kptsT,
                         float* __restrict__ vpts) {
    int n = blockIdx.x, t = threadIdx.x;   // 256 threads
    __shared__ float Rs[9], ts[3];
    if (t < 9) Rs[t] = rot[n * 9 + t];
    if (t < 3) ts[t] = trans[n * 3 + t];
    __syncthreads();
    if (t < 192) {
        int hh = t >> 4, d = t & 15;
        kT[((size_t)hh * 512 + n) * 16 + d] = kvraw[(size_t)n * 384 + hh * 32 + d];
        v[(size_t)n * 192 + t]              = kvraw[(size_t)n * 384 + hh * 32 + 16 + d];
    }
    if (t < 48) {   // q points
        float x  = qpraw[n * 144 + t];
        float y  = qpraw[n * 144 + 48 + t];
        float zc = qpraw[n * 144 + 96 + t];
        float gx = Rs[0] * x + Rs[1] * y + Rs[2] * zc + ts[0];
        float gy = Rs[3] * x + Rs[4] * y + Rs[5] * zc + ts[1];
        float gz = Rs[6] * x + Rs[7] * y + Rs[8] * zc + ts[2];
        int hh = t >> 2, p = t & 3;
        float* dst = qpts + ((size_t)n * 12 + hh) * 12 + p * 3;
        dst[0] = gx; dst[1] = gy; dst[2] = gz;
    }
    if (t >= 64 && t < 208) {  // kv points (144)
        int pf = t - 64;
        float x  = kvpraw[n * 432 + pf];
        float y  = kvpraw[n * 432 + 144 + pf];
        float zc = kvpraw[n * 432 + 288 + pf];
        float gx = Rs[0] * x + Rs[1] * y + Rs[2] * zc + ts[0];
        float gy = Rs[3] * x + Rs[4] * y + Rs[5] * zc + ts[1];
        float gz = Rs[6] * x + Rs[7] * y + Rs[8] * zc + ts[2];
        int hh = pf / 12, pp = pf % 12;
        if (pp < 4) {
            float* dst = kptsT + ((size_t)hh * 512 + n) * 12 + pp * 3;
            dst[0] = gx; dst[1] = gy; dst[2] = gz;
        } else {
            float* dst = vpts + (size_t)n * 288 + hh * 24 + (pp - 4) * 3;
            dst[0] = gx; dst[1] = gy; dst[2] = gz;
        }
    }
}

// ---------------- b[i][h][j] = z[i,j,:] @ Wb[:,h] + bb[h] ----------------
__global__ void bproj(const float* __restrict__ z,
                      const float* __restrict__ Wb,
                      const float* __restrict__ bb,
                      float* __restrict__ bmat) {
    __shared__ float Wb_s[12 * 128];
    __shared__ float bb_s[12];
    int tid = threadIdx.x;     // 128
    for (int idx = tid; idx < 1536; idx += 128) {
        int hh = idx >> 7, k = idx & 127;
        Wb_s[hh * 128 + k] = Wb[k * 12 + hh];
    }
    if (tid < 12) bb_s[tid] = bb[tid];
    __syncthreads();
    int warp = tid >> 5, lane = tid & 31;
    int row = blockIdx.x * 4 + warp;          // = i*512 + j
    const float* zr = z + (size_t)row * 128;
    float z0 = zr[lane], z1 = zr[lane + 32], z2 = zr[lane + 64], z3 = zr[lane + 96];
    float acc[12];
    #pragma unroll
    for (int hh = 0; hh < 12; hh++) {
        const float* w = Wb_s + hh * 128 + lane;
        acc[hh] = z0 * w[0] + z1 * w[32] + z2 * w[64] + z3 * w[96];
    }
    #pragma unroll
    for (int off = 16; off > 0; off >>= 1)
        #pragma unroll
        for (int hh = 0; hh < 12; hh++)
            acc[hh] += __shfl_xor_sync(0xffffffffu, acc[hh], off);
    int i = row >> 9, j = row & 511;
    #pragma unroll
    for (int hh = 0; hh < 12; hh++)
        if (lane == hh)
            bmat[((size_t)i * 12 + hh) * 512 + j] = acc[hh] + bb_s[hh];
}

// ---------------- logits + softmax per (i,h) ----------------
__global__ void logits_softmax(const float* __restrict__ q,
                               const float* __restrict__ kT,
                               const float* __restrict__ qpts,
                               const float* __restrict__ kptsT,
                               const float* __restrict__ bmat,
                               const float* __restrict__ mask,
                               const float* __restrict__ head_w,
                               float* __restrict__ a) {
    int i = blockIdx.x, h = blockIdx.y;
    int tid = threadIdx.x;    // 256
    __shared__ __align__(16) float q_s[16];
    __shared__ __align__(16) float qp_s[12];
    __shared__ float lg[512], red[256];
    __shared__ float s_hw, s_mi;
    if (tid < 16) q_s[tid] = q[(size_t)i * 192 + h * 16 + tid];
    if (tid < 12) qp_s[tid] = qpts[((size_t)i * 12 + h) * 12 + tid];
    if (tid == 0) {
        float w = head_w[h];
        float sp = (w > 20.f) ? w : log1pf(expf(w));        // softplus
        s_hw = sp * 0.13608276348795434f;                   // sqrt(1/54)
        s_mi = mask[i];
    }
    __syncthreads();
    const float c_qk = 0.14433756729740643f;  // sqrt(1/48)
    const float c_b  = 0.5773502691896258f;   // sqrt(1/3)
    float hw = s_hw, mi = s_mi;
    float4 q0 = *(const float4*)&q_s[0],  q1 = *(const float4*)&q_s[4];
    float4 q2 = *(const float4*)&q_s[8],  q3 = *(const float4*)&q_s[12];
    float4 p0 = *(const float4*)&qp_s[0], p1 = *(const float4*)&qp_s[4];
    float4 p2 = *(const float4*)&qp_s[8];
    #pragma unroll
    for (int r = 0; r < 2; r++) {
        int j = tid + r * 256;
        const float4* kp = (const float4*)(kT + ((size_t)h * 512 + j) * 16);
        float4 k0 = kp[0], k1 = kp[1], k2 = kp[2], k3 = kp[3];
        float qk = q0.x*k0.x + q0.y*k0.y + q0.z*k0.z + q0.w*k0.w
                 + q1.x*k1.x + q1.y*k1.y + q1.z*k1.z + q1.w*k1.w
                 + q2.x*k2.x + q2.y*k2.y + q2.z*k2.z + q2.w*k2.w
                 + q3.x*k3.x + q3.y*k3.y + q3.z*k3.z + q3.w*k3.w;
        const float4* kq = (const float4*)(kptsT + ((size_t)h * 512 + j) * 12);
        float4 c0 = kq[0], c1 = kq[1], c2 = kq[2];
        float d, pt = 0.f;
        d = p0.x - c0.x; pt += d * d;  d = p0.y - c0.y; pt += d * d;
        d = p0.z - c0.z; pt += d * d;  d = p0.w - c0.w; pt += d * d;
        d = p1.x - c1.x; pt += d * d;  d = p1.y - c1.y; pt += d * d;
        d = p1.z - c1.z; pt += d * d;  d = p1.w - c1.w; pt += d * d;
        d = p2.x - c2.x; pt += d * d;  d = p2.y - c2.y; pt += d * d;
        d = p2.z - c2.z; pt += d * d;  d = p2.w - c2.w; pt += d * d;
        lg[j] = qk * c_qk + c_b * bmat[((size_t)i * 12 + h) * 512 + j]
                - 0.5f * hw * pt + INF_ * (mi * mask[j] - 1.f);
    }
    __syncthreads();
    red[tid] = fmaxf(lg[tid], lg[tid + 256]);
    __syncthreads();
    for (int s = 128; s > 0; s >>= 1) {
        if (tid < s) red[tid] = fmaxf(red[tid], red[tid + s]);
        __syncthreads();
    }
    float mx = red[0];
    __syncthreads();
    float e0 = expf(lg[tid] - mx), e1 = expf(lg[tid + 256] - mx);
    lg[tid] = e0; lg[tid + 256] = e1;
    red[tid] = e0 + e1;
    __syncthreads();
    for (int s = 128; s > 0; s >>= 1) {
        if (tid < s) red[tid] += red[tid + s];
        __syncthreads();
    }
    float inv = 1.f / red[0];
    float* arow = a + ((size_t)i * 12 + h) * 512;
    arow[tid] = lg[tid] * inv;
    arow[tid + 256] = lg[tid + 256] * inv;
}

// ---------------- o = a@v ; o_pt = a@v_pts (+ inverse frame + norm), 4 rows/block ----------------
__global__ void att_out(const float* __restrict__ a,
                        const float* __restrict__ v,
                        const float* __restrict__ vpts,
                        const float* __restrict__ rot,
                        const float* __restrict__ trans,
                        float* __restrict__ cat) {
    int i0 = blockIdx.x * 4;
    int t = threadIdx.x;    // 480
    __shared__ float a_s[4][768];
    __shared__ float opts[4][288];
    __shared__ float Rs[4][9], ts[4][3];
    if (t < 36) Rs[t / 9][t % 9] = rot[(i0 + t / 9) * 9 + t % 9];
    if (t >= 64 && t < 76) {
        int r = (t - 64) / 3, cpt = (t - 64) % 3;
        ts[r][cpt] = trans[(i0 + r) * 3 + cpt];
    }
    float acc[4] = {0.f, 0.f, 0.f, 0.f};
    int h = (t < 192) ? (t >> 4) : ((t - 192) / 24);
    const float* src = (t < 192) ? (v + t) : (vpts + (t - 192));
    int stride = (t < 192) ? 192 : 288;
    for (int j0 = 0; j0 < 512; j0 += 64) {
        for (int idx = t; idx < 3072; idx += 480) {
            int r = idx >> 9 ? idx / 768 : idx / 768;   // r in 0..3
            int rem = idx - r * 768;
            int hh = rem >> 6, jj = rem & 63;
            a_s[r][rem] = a[((size_t)(i0 + r) * 12 + hh) * 512 + j0 + jj];
        }
        __syncthreads();
        const float* sp = src + (size_t)j0 * stride;
        const float* as0 = &a_s[0][h * 64];
        #pragma unroll 4
        for (int jj = 0; jj < 64; jj++) {
            float val = sp[(size_t)jj * stride];
            acc[0] += as0[jj]        * val;
            acc[1] += as0[768 + jj]  * val;
            acc[2] += as0[1536 + jj] * val;
            acc[3] += as0[2304 + jj] * val;
        }
        __syncthreads();
    }
    if (t >= 192) {
        #pragma unroll
        for (int r = 0; r < 4; r++) opts[r][t - 192] = acc[r];
    }
    __syncthreads();
    #pragma unroll
    for (int r = 0; r < 4; r++) {
        float* crow = cat + (size_t)(i0 + r) * 2112;
        if (t < 192) crow[t] = acc[r];
        if (t < 96) {
            int hh = t >> 3, p = t & 7;
            int base = hh * 24 + p * 3;
            float gx = opts[r][base]     - ts[r][0];
            float gy = opts[r][base + 1] - ts[r][1];
            float gz = opts[r][base + 2] - ts[r][2];
            float lx = Rs[r][0] * gx + Rs[r][3] * gy + Rs[r][6] * gz;   // R^T v
            float ly = Rs[r][1] * gx + Rs[r][4] * gy + Rs[r][7] * gz;
            float lz = Rs[r][2] * gx + Rs[r][5] * gy + Rs[r][8] * gz;
            crow[192 + t] = lx;
            crow[288 + t] = ly;
            crow[384 + t] = lz;
            crow[480 + t] = sqrtf(lx * lx + ly * ly + lz * lz + 1e-8f);
        }
    }
}

// ---------------- o_pair[i,h,c] = sum_j a[i,h,j] * z[i,j,c] ----------------
__global__ void opair(const float* __restrict__ a,
                      const float* __restrict__ z,
                      float* __restrict__ cat) {
    int i = blockIdx.x;
    int c = threadIdx.x;   // 128
    __shared__ __align__(16) float a_s[768];
    float acc[12] = {};
    for (int j0 = 0; j0 < 512; j0 += 64) {
        for (int idx = c; idx < 768; idx += 128) {
            int hh = idx >> 6, jj = idx & 63;
            a_s[idx] = a[((size_t)i * 12 + hh) * 512 + j0 + jj];
        }
        __syncthreads();
        const float* zp = z + ((size_t)i * 512 + j0) * 128 + c;
        #pragma unroll
        for (int jj4 = 0; jj4 < 16; jj4++) {
            int jj = jj4 * 4;
            float z0 = zp[(size_t)(jj + 0) * 128];
            float z1 = zp[(size_t)(jj + 1) * 128];
            float z2 = zp[(size_t)(jj + 2) * 128];
            float z3 = zp[(size_t)(jj + 3) * 128];
            #pragma unroll
            for (int hh = 0; hh < 12; hh++) {
                float4 av = *(const float4*)&a_s[hh * 64 + jj];
                acc[hh] += av.x * z0 + av.y * z1 + av.z * z2 + av.w * z3;
            }
        }
        __syncthreads();
    }
    float* crow = cat + (size_t)i * 2112 + 576;
    #pragma unroll
    for (int hh = 0; hh < 12; hh++)
        crow[hh * 128 + c] = acc[hh];
}

// ---------------- launch ----------------
extern "C" void kernel_launch(void* const* d_in, const int* in_sizes, int n_in,
                              void* d_out, int out_size) {
    const float* s      = (const float*)d_in[0];
    const float* z      = (const float*)d_in[1];
    const float* rot    = (const float*)d_in[2];
    const float* trans  = (const float*)d_in[3];
    const float* mask   = (const float*)d_in[4];
    const float* Wq     = (const float*)d_in[5];
    const float* bq     = (const float*)d_in[6];
    const float* Wkv    = (const float*)d_in[7];
    const float* bkv    = (const float*)d_in[8];
    const float* Wqp    = (const float*)d_in[9];
    const float* bqp    = (const float*)d_in[10];
    const float* Wkvp   = (const float*)d_in[11];
    const float* bkvp   = (const float*)d_in[12];
    const float* Wb     = (const float*)d_in[13];
    const float* bb     = (const float*)d_in[14];
    const float* head_w = (const float*)d_in[15];
    const float* Wout   = (const float*)d_in[16];
    const float* bout   = (const float*)d_in[17];
    float* out = (float*)d_out;

    float* base = nullptr;
    cudaGetSymbolAddress((void**)&base, g_scratch);
    float* q    = base + OFF_Q;
    float* kv   = base + OFF_KV;
    float* qpr  = base + OFF_QPR;
    float* kvpr = base + OFF_KVPR;
    float* kT   = base + OFF_KT;
    float* v    = base + OFF_V;
    float* qpts = base + OFF_QPTS;
    float* kpts = base + OFF_KPTS;
    float* vpts = base + OFF_VPTS;
    float* bmat = base + OFF_B;
    float* amat = base + OFF_A;
    float* cat  = base + OFF_CAT;

    Proj4 p;
    p.W[0] = Wq;   p.b[0] = bq;   p.C[0] = q;    p.Nout[0] = 192;
    p.W[1] = Wkv;  p.b[1] = bkv;  p.C[1] = kv;   p.Nout[1] = 384;
    p.W[2] = Wqp;  p.b[2] = bqp;  p.C[2] = qpr;  p.Nout[2] = 144;
    p.W[3] = Wkvp; p.b[3] = bkvp; p.C[3] = kvpr; p.Nout[3] = 432;

    proj_gemm<<<dim3(7, 8, 4), 256>>>(s, p);
    pointify<<<512, 256>>>(kv, qpr, kvpr, rot, trans, kT, v, qpts, kpts, vpts);
    bproj<<<65536, 128>>>(z, Wb, bb, bmat);
    logits_softmax<<<dim3(512, 12), 256>>>(q, kT, qpts, kpts, bmat, mask, head_w, amat);
    att_out<<<128, 480>>>(amat, v, vpts, rot, trans, cat);
    opair<<<512, 128>>>(amat, z, cat);
    gemm_one<<<dim3(16, 8), 256>>>(cat, Wout, bout, out, 2112, 1024);
}

// round 4
// speedup vs baseline: 1.5667x; 1.1128x over previous
#include <cuda_runtime.h>
#include <math.h>

#define INF_ 100000.0f

// ---------------- scratch ----------------
static constexpr size_t OFF_Q    = 0;                       // 512*192 q proj
static constexpr size_t OFF_KV   = OFF_Q    + 512*192;      // 512*384 raw kv proj
static constexpr size_t OFF_QPR  = OFF_KV   + 512*384;      // 512*144 raw q-pts proj
static constexpr size_t OFF_KVPR = OFF_QPR  + 512*144;      // 512*432 raw kv-pts proj
static constexpr size_t OFF_KEXT = OFF_KVPR + 512*432;      // [h][j][32]
static constexpr size_t OFF_QEXT = OFF_KEXT + (size_t)12*512*32; // [i][h][32]
static constexpr size_t OFF_V    = OFF_QEXT + (size_t)512*12*32; // [j][h][16]
static constexpr size_t OFF_VPTS = OFF_V    + 512*192;      // [j][h][24]
static constexpr size_t OFF_B    = OFF_VPTS + 512*288;      // [i][h][j] (pre-scaled by c_b)
static constexpr size_t OFF_A    = OFF_B    + (size_t)512*12*512;
static constexpr size_t OFF_CAT  = OFF_A    + (size_t)512*12*512; // [n][2112]
static constexpr size_t SCRATCH_TOTAL = OFF_CAT + (size_t)512*2112;

__device__ __align__(256) float g_scratch[SCRATCH_TOTAL];

union U64F2 { unsigned long long u; float2 f; };

#define FMA2(c, a, b) asm("fma.rn.f32x2 %0, %1, %2, %0;" : "+l"(c) : "l"(a), "l"(b))

// ---------------- 64x64x16 double-buffered fp32 GEMM with f32x2 FMA ----------------
// C[M,Nout] = A[M,K] @ W[K,Nout] + bias. M%64==0, K%16==0, Nout%4==0.
__device__ __forceinline__ void gemm64_body(const float* __restrict__ A,
                                            const float* __restrict__ W,
                                            const float* __restrict__ bias,
                                            float* __restrict__ C,
                                            int K, int Nout, int m0, int n0)
{
    __shared__ __align__(16) float As2[2][16][132];  // [kk][2*m] dup pairs, pad 132
    __shared__ __align__(16) float Ws[2][16][64];
    int tid = threadIdx.x;                 // 256
    int tx = tid & 15, ty = tid >> 4;
    int am = tid >> 2, ak = (tid & 3) << 2;
    int wk = tid >> 4, wn = (tid & 15) << 2;
    const float* Aptr = A + (size_t)(m0 + am) * K + ak;
    bool wval = (n0 + wn) < Nout;
    const float* Wptr = W + (size_t)wk * Nout + n0 + wn;

    float4 a0 = *(const float4*)Aptr;
    float4 w0 = wval ? *(const float4*)Wptr : make_float4(0.f, 0.f, 0.f, 0.f);
    As2[0][ak + 0][2*am] = a0.x; As2[0][ak + 0][2*am + 1] = a0.x;
    As2[0][ak + 1][2*am] = a0.y; As2[0][ak + 1][2*am + 1] = a0.y;
    As2[0][ak + 2][2*am] = a0.z; As2[0][ak + 2][2*am + 1] = a0.z;
    As2[0][ak + 3][2*am] = a0.w; As2[0][ak + 3][2*am + 1] = a0.w;
    *(float4*)&Ws[0][wk][wn] = w0;
    __syncthreads();

    unsigned long long acc[4][2] = {};   // {0,0} == {0.f,0.f}
    int buf = 0;
    int ntiles = K >> 4;
    for (int t = 0; t < ntiles; t++) {
        float4 aN, wN;
        bool more = (t + 1 < ntiles);
        if (more) {
            aN = *(const float4*)(Aptr + (size_t)(t + 1) * 16);
            wN = wval ? *(const float4*)(Wptr + (size_t)(t + 1) * 16 * Nout)
                      : make_float4(0.f, 0.f, 0.f, 0.f);
        }
        #pragma unroll
        for (int kk = 0; kk < 16; kk++) {
            ulonglong2 a01 = *(const ulonglong2*)&As2[buf][kk][ty << 3];
            ulonglong2 a23 = *(const ulonglong2*)&As2[buf][kk][(ty << 3) + 4];
            ulonglong2 wv  = *(const ulonglong2*)&Ws[buf][kk][tx << 2];
            FMA2(acc[0][0], a01.x, wv.x); FMA2(acc[0][1], a01.x, wv.y);
            FMA2(acc[1][0], a01.y, wv.x); FMA2(acc[1][1], a01.y, wv.y);
            FMA2(acc[2][0], a23.x, wv.x); FMA2(acc[2][1], a23.x, wv.y);
            FMA2(acc[3][0], a23.y, wv.x); FMA2(acc[3][1], a23.y, wv.y);
        }
        if (more) {
            int nb = buf ^ 1;
            As2[nb][ak + 0][2*am] = aN.x; As2[nb][ak + 0][2*am + 1] = aN.x;
            As2[nb][ak + 1][2*am] = aN.y; As2[nb][ak + 1][2*am + 1] = aN.y;
            As2[nb][ak + 2][2*am] = aN.z; As2[nb][ak + 2][2*am + 1] = aN.z;
            As2[nb][ak + 3][2*am] = aN.w; As2[nb][ak + 3][2*am + 1] = aN.w;
            *(float4*)&Ws[nb][wk][wn] = wN;
            __syncthreads();
            buf = nb;
        }
    }
    if (wval) {
        float4 bv = *(const float4*)&bias[n0 + (tx << 2)];
        #pragma unroll
        for (int u = 0; u < 4; u++) {
            U64F2 p0, p1;
            p0.u = acc[u][0]; p1.u = acc[u][1];
            float4 o;
            o.x = p0.f.x + bv.x; o.y = p0.f.y + bv.y;
            o.z = p1.f.x + bv.z; o.w = p1.f.y + bv.w;
            *(float4*)&C[(size_t)(m0 + (ty << 2) + u) * Nout + n0 + (tx << 2)] = o;
        }
    }
}

struct Proj4 {
    const float* W[4];
    const float* b[4];
    float* C[4];
    int Nout[4];
};

__global__ void proj_gemm(const float* __restrict__ s, Proj4 p) {
    int g = blockIdx.z;
    int Nout = p.Nout[g];
    int n0 = blockIdx.x * 64;
    if (n0 >= Nout) return;
    gemm64_body(s, p.W[g], p.b[g], p.C[g], 1024, Nout, blockIdx.y * 64, n0);
}

__global__ void gemm_one(const float* __restrict__ A, const float* __restrict__ W,
                         const float* __restrict__ bias, float* __restrict__ C,
                         int K, int Nout) {
    gemm64_body(A, W, bias, C, K, Nout, blockIdx.y * 64, blockIdx.x * 64);
}

// ---------------- pointify: build kext/qext/v/vpts ----------------
__global__ void pointify(const float* __restrict__ kvraw,
                         const float* __restrict__ qraw,
                         const float* __restrict__ qpraw,
                         const float* __restrict__ kvpraw,
                         const float* __restrict__ rot,
                         const float* __restrict__ trans,
                         const float* __restrict__ head_w,
                         float* __restrict__ kext, float* __restrict__ qext,
                         float* __restrict__ v, float* __restrict__ vpts) {
    int n = blockIdx.x, t = threadIdx.x;   // 256 threads
    __shared__ float Rs[9], ts[3], qg[144], kg[432], hw_s[12];
    if (t < 9) Rs[t] = rot[n * 9 + t];
    if (t >= 16 && t < 19) ts[t - 16] = trans[n * 3 + (t - 16)];
    if (t >= 32 && t < 44) {
        float w = head_w[t - 32];
        float sp = (w > 20.f) ? w : log1pf(expf(w));
        hw_s[t - 32] = sp * 0.13608276348795434f;   // sqrt(1/54)
    }
    __syncthreads();
    if (t < 48) {   // q points (h*4+p flattened)
        float x  = qpraw[n * 144 + t];
        float y  = qpraw[n * 144 + 48 + t];
        float zc = qpraw[n * 144 + 96 + t];
        qg[t * 3 + 0] = Rs[0] * x + Rs[1] * y + Rs[2] * zc + ts[0];
        qg[t * 3 + 1] = Rs[3] * x + Rs[4] * y + Rs[5] * zc + ts[1];
        qg[t * 3 + 2] = Rs[6] * x + Rs[7] * y + Rs[8] * zc + ts[2];
    }
    if (t >= 64 && t < 208) {  // kv points (h*12+pp flattened, 144)
        int pf = t - 64;
        float x  = kvpraw[n * 432 + pf];
        float y  = kvpraw[n * 432 + 144 + pf];
        float zc = kvpraw[n * 432 + 288 + pf];
        kg[pf * 3 + 0] = Rs[0] * x + Rs[1] * y + Rs[2] * zc + ts[0];
        kg[pf * 3 + 1] = Rs[3] * x + Rs[4] * y + Rs[5] * zc + ts[1];
        kg[pf * 3 + 2] = Rs[6] * x + Rs[7] * y + Rs[8] * zc + ts[2];
    }
    __syncthreads();
    if (t < 192) {
        int hh = t >> 4, d = t & 15;
        kext[((size_t)hh * 512 + n) * 32 + d] = kvraw[(size_t)n * 384 + hh * 32 + d];
        v[(size_t)n * 192 + t]                = kvraw[(size_t)n * 384 + hh * 32 + 16 + d];
        qext[((size_t)n * 12 + hh) * 32 + d]  = 0.14433756729740643f * qraw[(size_t)n * 192 + t];
    }
    for (int idx = t; idx < 288; idx += 256) {
        int hh = idx / 24, rem = idx % 24;       // rem = (pp-4)*3 + c
        vpts[(size_t)n * 288 + idx] = kg[hh * 36 + 12 + rem];
    }
    if (t < 12) {
        int hh = t; float hw = hw_s[hh];
        float Sk = 0.f, Sq = 0.f;
        float* ke = &kext[((size_t)hh * 512 + n) * 32];
        float* qe = &qext[((size_t)n * 12 + hh) * 32];
        #pragma unroll
        for (int u = 0; u < 12; u++) {
            float kvv = kg[hh * 36 + u];  Sk += kvv * kvv;  ke[16 + u] = kvv;
            float qvv = qg[hh * 12 + u];  Sq += qvv * qvv;  qe[16 + u] = hw * qvv;
        }
        // mask handled OUTSIDE the dot product (precision: keep 1e5 terms
        // out of the fp32 accumulator)
        ke[28] = -0.5f * hw * Sk; ke[29] = 1.f; ke[30] = 0.f; ke[31] = 0.f;
        qe[28] = 1.f; qe[29] = -0.5f * hw * Sq; qe[30] = 0.f; qe[31] = 0.f;
    }
}

// ---------------- bproj2: bmat[i][h][j] = c_b*(z[i,j,:]@Wb + bb) ----------------
__global__ void bproj2(const float* __restrict__ z,
                       const float* __restrict__ Wb,
                       const float* __restrict__ bb,
                       float* __restrict__ bmat) {
    extern __shared__ float zs[];           // [256][132]
    __shared__ float Wb_s[128 * 12];
    __shared__ float bb_s[12];
    const float c_b = 0.5773502691896258f;  // sqrt(1/3)
    int t = threadIdx.x;                    // 256
    size_t r0 = (size_t)blockIdx.x * 256;
    for (int idx = t; idx < 1536; idx += 256) Wb_s[idx] = c_b * Wb[idx];
    if (t < 12) bb_s[t] = c_b * bb[t];
    for (int idx = t; idx < 8192; idx += 256) {
        int row = idx >> 5, c4 = (idx & 31) << 2;
        float4 vv = *(const float4*)&z[(r0 + row) * 128 + c4];
        *(float4*)&zs[row * 132 + c4] = vv;
    }
    __syncthreads();
    int rg = t >> 2, hg = (t & 3) * 3;
    float acc[4][3] = {};
    #pragma unroll 2
    for (int d = 0; d < 128; d++) {
        float w0 = Wb_s[d * 12 + hg];
        float w1 = Wb_s[d * 12 + hg + 1];
        float w2 = Wb_s[d * 12 + hg + 2];
        #pragma unroll
        for (int rr = 0; rr < 4; rr++) {
            float zv = zs[(rg + 64 * rr) * 132 + d];
            acc[rr][0] += zv * w0;
            acc[rr][1] += zv * w1;
            acc[rr][2] += zv * w2;
        }
    }
    int i = (int)(r0 >> 9);
    int jbase = (int)(r0 & 511);
    #pragma unroll
    for (int rr = 0; rr < 4; rr++) {
        int j = jbase + rg + 64 * rr;
        #pragma unroll
        for (int hh = 0; hh < 3; hh++)
            bmat[((size_t)i * 12 + hg + hh) * 512 + j] = acc[rr][hh] + bb_s[hg + hh];
    }
}

// ---------------- logits (rank-30 GEMM) + mask bias + softmax ----------------
__global__ void logits_softmax(const float* __restrict__ qext,
                               const float* __restrict__ kext,
                               const float* __restrict__ bmat,
                               const float* __restrict__ mask,
                               float* __restrict__ a) {
    int i0 = blockIdx.x * 32, h = blockIdx.y;
    int t = threadIdx.x;     // 256
    int w = t >> 5, l = t & 31;
    __shared__ __align__(16) float qe[32][32];
    __shared__ __align__(16) float ke[32][65];
    __shared__ __align__(16) float b_s[32][64];
    __shared__ float ms[512], mi_s[32];
    // load qext rows + masks
    {
        int r = t >> 3, d4 = (t & 7) << 2;
        *(float4*)&qe[r][d4] = *(const float4*)&qext[((size_t)(i0 + r) * 12 + h) * 32 + d4];
    }
    for (int idx = t; idx < 512; idx += 256) ms[idx] = mask[idx];
    if (t < 32) mi_s[t] = mask[i0 + t];
    float rmax[4] = {-3.4e38f, -3.4e38f, -3.4e38f, -3.4e38f};
    for (int jt = 0; jt < 8; jt++) {
        int j0 = jt * 64;
        __syncthreads();
        #pragma unroll
        for (int idx = t; idx < 512; idx += 256) {
            int jr = idx >> 3, d4 = (idx & 7) << 2;
            float4 kv = *(const float4*)&kext[((size_t)h * 512 + j0 + jr) * 32 + d4];
            ke[d4 + 0][jr] = kv.x; ke[d4 + 1][jr] = kv.y;
            ke[d4 + 2][jr] = kv.z; ke[d4 + 3][jr] = kv.w;
        }
        #pragma unroll
        for (int idx = t; idx < 512; idx += 256) {
            int r = idx >> 4, c4 = (idx & 15) << 2;
            *(float4*)&b_s[r][c4] =
                *(const float4*)&bmat[((size_t)(i0 + r) * 12 + h) * 512 + j0 + c4];
        }
        __syncthreads();
        float acc[4][2] = {};
        #pragma unroll 4
        for (int d = 0; d < 30; d++) {
            float k0 = ke[d][l], k1 = ke[d][l + 32];
            #pragma unroll
            for (int rr = 0; rr < 4; rr++) {
                float qv = qe[(w << 2) + rr][d];
                acc[rr][0] += qv * k0;
                acc[rr][1] += qv * k1;
            }
        }
        float mj0 = ms[j0 + l], mj1 = ms[j0 + l + 32];
        #pragma unroll
        for (int rr = 0; rr < 4; rr++) {
            int r = (w << 2) + rr;
            float mi = mi_s[r];
            float lg0 = acc[rr][0] + b_s[r][l]      + INF_ * fmaf(mi, mj0, -1.f);
            float lg1 = acc[rr][1] + b_s[r][l + 32] + INF_ * fmaf(mi, mj1, -1.f);
            float* arow = a + ((size_t)(i0 + r) * 12 + h) * 512 + j0;
            arow[l] = lg0;
            arow[l + 32] = lg1;
            rmax[rr] = fmaxf(rmax[rr], fmaxf(lg0, lg1));
        }
    }
    __syncthreads();   // make all logit stores visible (CTA scope)
    #pragma unroll
    for (int off = 16; off > 0; off >>= 1)
        #pragma unroll
        for (int rr = 0; rr < 4; rr++)
            rmax[rr] = fmaxf(rmax[rr], __shfl_xor_sync(0xffffffffu, rmax[rr], off));
    #pragma unroll
    for (int rr = 0; rr < 4; rr++) {
        float* arow = a + ((size_t)(i0 + (w << 2) + rr) * 12 + h) * 512;
        float mx = rmax[rr];
        float sum = 0.f;
        #pragma unroll
        for (int c = l; c < 512; c += 32) sum += __expf(arow[c] - mx);
        #pragma unroll
        for (int off = 16; off > 0; off >>= 1)
            sum += __shfl_xor_sync(0xffffffffu, sum, off);
        float inv = 1.f / sum;
        #pragma unroll
        for (int c = l; c < 512; c += 32) arow[c] = __expf(arow[c] - mx) * inv;
    }
}

// ---------------- o = a@v ; o_pt = a@v_pts (+ inverse frame + norm), 4 rows/block ----------------
__global__ void att_out(const float* __restrict__ a,
                        const float* __restrict__ v,
                        const float* __restrict__ vpts,
                        const float* __restrict__ rot,
                        const float* __restrict__ trans,
                        float* __restrict__ cat) {
    int i0 = blockIdx.x * 4;
    int t = threadIdx.x;    // 480
    __shared__ float a_s[4][768];
    __shared__ float opts[4][288];
    __shared__ float Rs[4][9], ts[4][3];
    if (t < 36) Rs[t / 9][t % 9] = rot[(i0 + t / 9) * 9 + t % 9];
    if (t >= 64 && t < 76) {
        int r = (t - 64) / 3, cpt = (t - 64) % 3;
        ts[r][cpt] = trans[(i0 + r) * 3 + cpt];
    }
    float acc[4] = {0.f, 0.f, 0.f, 0.f};
    int h = (t < 192) ? (t >> 4) : ((t - 192) / 24);
    const float* src = (t < 192) ? (v + t) : (vpts + (t - 192));
    int stride = (t < 192) ? 192 : 288;
    for (int j0 = 0; j0 < 512; j0 += 64) {
        for (int idx = t; idx < 3072; idx += 480) {
            int r = idx / 768;
            int rem = idx - r * 768;
            int hh = rem >> 6, jj = rem & 63;
            a_s[r][rem] = a[((size_t)(i0 + r) * 12 + hh) * 512 + j0 + jj];
        }
        __syncthreads();
        const float* sp = src + (size_t)j0 * stride;
        const float* as0 = &a_s[0][h * 64];
        #pragma unroll 4
        for (int jj = 0; jj < 64; jj++) {
            float val = sp[(size_t)jj * stride];
            acc[0] += as0[jj]        * val;
            acc[1] += as0[768 + jj]  * val;
            acc[2] += as0[1536 + jj] * val;
            acc[3] += as0[2304 + jj] * val;
        }
        __syncthreads();
    }
    if (t >= 192) {
        #pragma unroll
        for (int r = 0; r < 4; r++) opts[r][t - 192] = acc[r];
    }
    __syncthreads();
    #pragma unroll
    for (int r = 0; r < 4; r++) {
        float* crow = cat + (size_t)(i0 + r) * 2112;
        if (t < 192) crow[t] = acc[r];
        if (t < 96) {
            int hh = t >> 3, p = t & 7;
            int base = hh * 24 + p * 3;
            float gx = opts[r][base]     - ts[r][0];
            float gy = opts[r][base + 1] - ts[r][1];
            float gz = opts[r][base + 2] - ts[r][2];
            float lx = Rs[r][0] * gx + Rs[r][3] * gy + Rs[r][6] * gz;   // R^T v
            float ly = Rs[r][1] * gx + Rs[r][4] * gy + Rs[r][7] * gz;
            float lz = Rs[r][2] * gx + Rs[r][5] * gy + Rs[r][8] * gz;
            crow[192 + t] = lx;
            crow[288 + t] = ly;
            crow[384 + t] = lz;
            crow[480 + t] = sqrtf(lx * lx + ly * ly + lz * lz + 1e-8f);
        }
    }
}

// ---------------- o_pair[i,h,c] = sum_j a[i,h,j] * z[i,j,c] ----------------
__global__ void opair(const float* __restrict__ a,
                      const float* __restrict__ z,
                      float* __restrict__ cat) {
    int i = blockIdx.x;
    int c = threadIdx.x;   // 128
    __shared__ __align__(16) float a_s[768];
    float acc[12] = {};
    for (int j0 = 0; j0 < 512; j0 += 64) {
        for (int idx = c; idx < 768; idx += 128) {
            int hh = idx >> 6, jj = idx & 63;
            a_s[idx] = a[((size_t)i * 12 + hh) * 512 + j0 + jj];
        }
        __syncthreads();
        const float* zp = z + ((size_t)i * 512 + j0) * 128 + c;
        #pragma unroll
        for (int jj4 = 0; jj4 < 16; jj4++) {
            int jj = jj4 * 4;
            float z0 = zp[(size_t)(jj + 0) * 128];
            float z1 = zp[(size_t)(jj + 1) * 128];
            float z2 = zp[(size_t)(jj + 2) * 128];
            float z3 = zp[(size_t)(jj + 3) * 128];
            #pragma unroll
            for (int hh = 0; hh < 12; hh++) {
                float4 av = *(const float4*)&a_s[hh * 64 + jj];
                acc[hh] += av.x * z0 + av.y * z1 + av.z * z2 + av.w * z3;
            }
        }
        __syncthreads();
    }
    float* crow = cat + (size_t)i * 2112 + 576;
    #pragma unroll
    for (int hh = 0; hh < 12; hh++)
        crow[hh * 128 + c] = acc[hh];
}

// ---------------- launch ----------------
extern "C" void kernel_launch(void* const* d_in, const int* in_sizes, int n_in,
                              void* d_out, int out_size) {
    const float* s      = (const float*)d_in[0];
    const float* z      = (const float*)d_in[1];
    const float* rot    = (const float*)d_in[2];
    const float* trans  = (const float*)d_in[3];
    const float* mask   = (const float*)d_in[4];
    const float* Wq     = (const float*)d_in[5];
    const float* bq     = (const float*)d_in[6];
    const float* Wkv    = (const float*)d_in[7];
    const float* bkv    = (const float*)d_in[8];
    const float* Wqp    = (const float*)d_in[9];
    const float* bqp    = (const float*)d_in[10];
    const float* Wkvp   = (const float*)d_in[11];
    const float* bkvp   = (const float*)d_in[12];
    const float* Wb     = (const float*)d_in[13];
    const float* bb     = (const float*)d_in[14];
    const float* head_w = (const float*)d_in[15];
    const float* Wout   = (const float*)d_in[16];
    const float* bout   = (const float*)d_in[17];
    float* out = (float*)d_out;

    float* base = nullptr;
    cudaGetSymbolAddress((void**)&base, g_scratch);
    float* q    = base + OFF_Q;
    float* kv   = base + OFF_KV;
    float* qpr  = base + OFF_QPR;
    float* kvpr = base + OFF_KVPR;
    float* kext = base + OFF_KEXT;
    float* qext = base + OFF_QEXT;
    float* v    = base + OFF_V;
    float* vpts = base + OFF_VPTS;
    float* bmat = base + OFF_B;
    float* amat = base + OFF_A;
    float* cat  = base + OFF_CAT;

    Proj4 p;
    p.W[0] = Wq;   p.b[0] = bq;   p.C[0] = q;    p.Nout[0] = 192;
    p.W[1] = Wkv;  p.b[1] = bkv;  p.C[1] = kv;   p.Nout[1] = 384;
    p.W[2] = Wqp;  p.b[2] = bqp;  p.C[2] = qpr;  p.Nout[2] = 144;
    p.W[3] = Wkvp; p.b[3] = bkvp; p.C[3] = kvpr; p.Nout[3] = 432;

    static int smem_set = 0;
    if (!smem_set) {
        cudaFuncSetAttribute(bproj2, cudaFuncAttributeMaxDynamicSharedMemorySize,
                             256 * 132 * 4);
        smem_set = 1;
    }

    proj_gemm<<<dim3(7, 8, 4), 256>>>(s, p);
    pointify<<<512, 256>>>(kv, q, qpr, kvpr, rot, trans, head_w,
                           kext, qext, v, vpts);
    bproj2<<<1024, 256, 256 * 132 * 4>>>(z, Wb, bb, bmat);
    logits_softmax<<<dim3(16, 12), 256>>>(qext, kext, bmat, mask, amat);
    att_out<<<128, 480>>>(amat, v, vpts, rot, trans, cat);
    opair<<<512, 128>>>(amat, z, cat);
    gemm_one<<<dim3(16, 8), 256>>>(cat, Wout, bout, out, 2112, 1024);
}

// round 6
// speedup vs baseline: 1.9723x; 1.2589x over previous
#include <cuda_runtime.h>
#include <cuda_bf16.h>
#include <math.h>
#include <stdint.h>

#define INF_ 100000.0f

// ================= scratch (floats) =================
static constexpr size_t OFF_PROJ  = 0;                          // 512*1152
static constexpr size_t OFF_KEXT  = OFF_PROJ  + (size_t)512*1152;      // 12*512*32
static constexpr size_t OFF_QEXT  = OFF_KEXT  + (size_t)12*512*32;     // 512*12*32
static constexpr size_t OFF_V     = OFF_QEXT  + (size_t)512*12*32;     // 512*192
static constexpr size_t OFF_VPTS  = OFF_V     + (size_t)512*192;       // 512*288
static constexpr size_t OFF_B     = OFF_VPTS  + (size_t)512*288;       // 512*12*512
static constexpr size_t OFF_A     = OFF_B     + (size_t)512*12*512;    // 512*12*512
static constexpr size_t OFF_CAT   = OFF_A     + (size_t)512*12*512;    // 512*2112
static constexpr size_t OFF_AINT  = OFF_CAT   + (size_t)512*2112;      // bf16 512*3072
static constexpr size_t OFF_WINTP = OFF_AINT  + (size_t)512*3072/2;    // bf16 1152*3072
static constexpr size_t OFF_CINT  = OFF_WINTP + (size_t)1152*3072/2;   // bf16 512*6336
static constexpr size_t OFF_WINTO = OFF_CINT  + (size_t)512*6336/2;    // bf16 1024*6336
static constexpr size_t OFF_BIASA = OFF_WINTO + (size_t)1024*6336/2;   // 1152
static constexpr size_t SCRATCH_TOTAL = OFF_BIASA + 1152;

__device__ __align__(256) float g_scratch[SCRATCH_TOTAL];

__device__ __forceinline__ uint32_t smem_u32(const void* p) {
    uint32_t a;
    asm("{ .reg .u64 t; cvta.to.shared.u64 t, %1; cvt.u32.u64 %0, t; }" : "=r"(a) : "l"(p));
    return a;
}

// ================= split kernels (fp32 -> interleaved bf16 hi/lo) =================
// A-side pattern per k: [hi, lo, hi].  dst[row][3K]
__global__ void split_rows(const float* __restrict__ src, __nv_bfloat16* __restrict__ dst, int K) {
    int row = blockIdx.x, tid = threadIdx.x;
    const float* s = src + (size_t)row * K;
    uint32_t* d = (uint32_t*)(dst + (size_t)row * 3 * K);
    for (int p = tid; p < (K >> 1); p += blockDim.x) {
        float a0 = s[2 * p], a1 = s[2 * p + 1];
        __nv_bfloat16 h0 = __float2bfloat16(a0);
        __nv_bfloat16 l0 = __float2bfloat16(a0 - __bfloat162float(h0));
        __nv_bfloat16 h1 = __float2bfloat16(a1);
        __nv_bfloat16 l1 = __float2bfloat16(a1 - __bfloat162float(h1));
        uint32_t uh0 = __bfloat16_as_ushort(h0), ul0 = __bfloat16_as_ushort(l0);
        uint32_t uh1 = __bfloat16_as_ushort(h1), ul1 = __bfloat16_as_ushort(l1);
        d[3 * p + 0] = uh0 | (ul0 << 16);   // [hi0, lo0]
        d[3 * p + 1] = uh0 | (uh1 << 16);   // [hi0, hi1]
        d[3 * p + 2] = ul1 | (uh1 << 16);   // [lo1, hi1]
    }
}

// W-side pattern per k: [hi, hi, lo], with transpose: dst[n][3K], src W[K][N]
__global__ void split_w(const float* __restrict__ W, __nv_bfloat16* __restrict__ dst,
                        int N, int Kp, int rowoff) {
    int kp = blockIdx.x;                 // k-pair index
    int n = blockIdx.y * 256 + threadIdx.x;
    if (n >= N) return;
    float a0 = W[(size_t)(2 * kp) * N + n];
    float a1 = W[(size_t)(2 * kp + 1) * N + n];
    __nv_bfloat16 h0 = __float2bfloat16(a0);
    __nv_bfloat16 l0 = __float2bfloat16(a0 - __bfloat162float(h0));
    __nv_bfloat16 h1 = __float2bfloat16(a1);
    __nv_bfloat16 l1 = __float2bfloat16(a1 - __bfloat162float(h1));
    uint32_t uh0 = __bfloat16_as_ushort(h0), ul0 = __bfloat16_as_ushort(l0);
    uint32_t uh1 = __bfloat16_as_ushort(h1), ul1 = __bfloat16_as_ushort(l1);
    uint32_t* d = (uint32_t*)(dst + (size_t)(rowoff + n) * Kp) + 3 * kp;
    d[0] = uh0 | (uh0 << 16);   // [hi0, hi0]
    d[1] = ul0 | (uh1 << 16);   // [lo0, hi1]
    d[2] = uh1 | (ul1 << 16);   // [hi1, lo1]
}

__global__ void concat_bias(const float* __restrict__ b0, const float* __restrict__ b1,
                            const float* __restrict__ b2, const float* __restrict__ b3,
                            float* __restrict__ out) {
    int t = blockIdx.x * 256 + threadIdx.x;
    if (t >= 1152) return;
    float v;
    if (t < 192) v = b0[t];
    else if (t < 576) v = b1[t - 192];
    else if (t < 720) v = b2[t - 576];
    else v = b3[t - 720];
    out[t] = v;
}

// ================= warp-MMA bf16 GEMM =================
// C[M][Nld] = Aint[M][Kp] @ Bint[N][Kp]^T + bias
// CTA tile 64x64, 4 warps (32x32 each: 2x4 m16n8k16), K-chunk 64, double-buffered.
#define ROWP 72                        // padded row length in bf16 (144 B, conflict-free LDSM)
#define BUFB (64 * ROWP * 2)           // 9216 bytes per tile

__global__ void __launch_bounds__(128) mma_gemm(const __nv_bfloat16* __restrict__ A,
                                                const __nv_bfloat16* __restrict__ B,
                                                const float* __restrict__ bias,
                                                float* __restrict__ C,
                                                int Kp, int Nld) {
    __shared__ __align__(16) __nv_bfloat16 sA[2][64][ROWP];
    __shared__ __align__(16) __nv_bfloat16 sB[2][64][ROWP];
    int tid = threadIdx.x, wid = tid >> 5, lane = tid & 31;
    int m0 = blockIdx.y * 64, n0 = blockIdx.x * 64;
    int Mw = (wid >> 1) * 32, Nw = (wid & 1) * 32;

    uint32_t sA_base = smem_u32(&sA[0][0][0]);
    uint32_t sB_base = smem_u32(&sB[0][0][0]);
    // ldmatrix addresses
    uint32_t aoff0 = ((uint32_t)((Mw + (lane & 15)) * ROWP + ((lane >> 4) << 3))) << 1;
    uint32_t boff0 = ((uint32_t)((Nw + (lane & 7)) * ROWP + (lane & 8))) << 1;

    const char* Abase = (const char*)A;
    const char* Bbase = (const char*)B;
    int ntiles = Kp >> 6;

    // load chunk 0
    #pragma unroll
    for (int u = 0; u < 4; u++) {
        int idx = tid + u * 128;
        int row = idx >> 3, c = idx & 7;
        *(uint4*)((char*)&sA[0][0][0] + row * (ROWP * 2) + c * 16) =
            *(const uint4*)(Abase + ((size_t)(m0 + row) * Kp + c * 8) * 2);
        *(uint4*)((char*)&sB[0][0][0] + row * (ROWP * 2) + c * 16) =
            *(const uint4*)(Bbase + ((size_t)(n0 + row) * Kp + c * 8) * 2);
    }
    __syncthreads();

    float acc[2][4][4] = {};
    for (int t = 0; t < ntiles; t++) {
        int b = t & 1;
        uint4 pa[4], pb[4];
        bool more = (t + 1) < ntiles;
        if (more) {
            #pragma unroll
            for (int u = 0; u < 4; u++) {
                int idx = tid + u * 128;
                int row = idx >> 3, c = idx & 7;
                pa[u] = *(const uint4*)(Abase + ((size_t)(m0 + row) * Kp + (t + 1) * 64 + c * 8) * 2);
                pb[u] = *(const uint4*)(Bbase + ((size_t)(n0 + row) * Kp + (t + 1) * 64 + c * 8) * 2);
            }
        }
        #pragma unroll
        for (int ks = 0; ks < 4; ks++) {
            uint32_t kb = (uint32_t)ks << 5;     // 16 bf16 = 32 bytes
            uint32_t af[2][4], bfr[4][2];
            #pragma unroll
            for (int mt = 0; mt < 2; mt++) {
                uint32_t ad = sA_base + b * BUFB + aoff0 + mt * (16 * ROWP * 2) + kb;
                asm volatile("ldmatrix.sync.aligned.m8n8.x4.shared.b16 {%0,%1,%2,%3}, [%4];"
                    : "=r"(af[mt][0]), "=r"(af[mt][1]), "=r"(af[mt][2]), "=r"(af[mt][3])
                    : "r"(ad));
            }
            #pragma unroll
            for (int nt = 0; nt < 4; nt++) {
                uint32_t bd = sB_base + b * BUFB + boff0 + nt * (8 * ROWP * 2) + kb;
                asm volatile("ldmatrix.sync.aligned.m8n8.x2.shared.b16 {%0,%1}, [%2];"
                    : "=r"(bfr[nt][0]), "=r"(bfr[nt][1]) : "r"(bd));
            }
            #pragma unroll
            for (int mt = 0; mt < 2; mt++)
                #pragma unroll
                for (int nt = 0; nt < 4; nt++)
                    asm volatile("mma.sync.aligned.m16n8k16.row.col.f32.bf16.bf16.f32 "
                        "{%0,%1,%2,%3}, {%4,%5,%6,%7}, {%8,%9}, {%0,%1,%2,%3};"
                        : "+f"(acc[mt][nt][0]), "+f"(acc[mt][nt][1]),
                          "+f"(acc[mt][nt][2]), "+f"(acc[mt][nt][3])
                        : "r"(af[mt][0]), "r"(af[mt][1]), "r"(af[mt][2]), "r"(af[mt][3]),
                          "r"(bfr[nt][0]), "r"(bfr[nt][1]));
        }
        if (more) {
            __syncthreads();
            #pragma unroll
            for (int u = 0; u < 4; u++) {
                int idx = tid + u * 128;
                int row = idx >> 3, c = idx & 7;
                *(uint4*)((char*)&sA[b ^ 1][0][0] + row * (ROWP * 2) + c * 16) = pa[u];
                *(uint4*)((char*)&sB[b ^ 1][0][0] + row * (ROWP * 2) + c * 16) = pb[u];
            }
            __syncthreads();
        }
    }

    // epilogue
    #pragma unroll
    for (int mt = 0; mt < 2; mt++) {
        int r = m0 + Mw + mt * 16 + (lane >> 2);
        #pragma unroll
        for (int nt = 0; nt < 4; nt++) {
            int col = n0 + Nw + nt * 8 + ((lane & 3) << 1);
            float b0v = bias[col], b1v = bias[col + 1];
            float2 o0 = { acc[mt][nt][0] + b0v, acc[mt][nt][1] + b1v };
            float2 o1 = { acc[mt][nt][2] + b0v, acc[mt][nt][3] + b1v };
            *(float2*)&C[(size_t)r * Nld + col] = o0;
            *(float2*)&C[(size_t)(r + 8) * Nld + col] = o1;
        }
    }
}

// ================= pointify: build kext/qext/v/vpts from fused proj =================
// proj row layout: [q(192) | kv(384) | qpr(144) | kvpr(432)], stride 1152
__global__ void pointify(const float* __restrict__ proj,
                         const float* __restrict__ rot,
                         const float* __restrict__ trans,
                         const float* __restrict__ head_w,
                         float* __restrict__ kext, float* __restrict__ qext,
                         float* __restrict__ v, float* __restrict__ vpts) {
    int n = blockIdx.x, t = threadIdx.x;   // 256 threads
    __shared__ float Rs[9], ts[3], qg[144], kg[432], hw_s[12];
    const float* prow = proj + (size_t)n * 1152;
    if (t < 9) Rs[t] = rot[n * 9 + t];
    if (t >= 16 && t < 19) ts[t - 16] = trans[n * 3 + (t - 16)];
    if (t >= 32 && t < 44) {
        float w = head_w[t - 32];
        float sp = (w > 20.f) ? w : log1pf(expf(w));
        hw_s[t - 32] = sp * 0.13608276348795434f;   // sqrt(1/54)
    }
    __syncthreads();
    if (t < 48) {   // q points
        float x  = prow[576 + t];
        float y  = prow[576 + 48 + t];
        float zc = prow[576 + 96 + t];
        qg[t * 3 + 0] = Rs[0] * x + Rs[1] * y + Rs[2] * zc + ts[0];
        qg[t * 3 + 1] = Rs[3] * x + Rs[4] * y + Rs[5] * zc + ts[1];
        qg[t * 3 + 2] = Rs[6] * x + Rs[7] * y + Rs[8] * zc + ts[2];
    }
    if (t >= 64 && t < 208) {  // kv points (144)
        int pf = t - 64;
        float x  = prow[720 + pf];
        float y  = prow[720 + 144 + pf];
        float zc = prow[720 + 288 + pf];
        kg[pf * 3 + 0] = Rs[0] * x + Rs[1] * y + Rs[2] * zc + ts[0];
        kg[pf * 3 + 1] = Rs[3] * x + Rs[4] * y + Rs[5] * zc + ts[1];
        kg[pf * 3 + 2] = Rs[6] * x + Rs[7] * y + Rs[8] * zc + ts[2];
    }
    __syncthreads();
    if (t < 192) {
        int hh = t >> 4, d = t & 15;
        kext[((size_t)hh * 512 + n) * 32 + d] = prow[192 + hh * 32 + d];
        v[(size_t)n * 192 + t]                = prow[192 + hh * 32 + 16 + d];
        qext[((size_t)n * 12 + hh) * 32 + d]  = 0.14433756729740643f * prow[t];
    }
    for (int idx = t; idx < 288; idx += 256) {
        int hh = idx / 24, rem = idx % 24;
        vpts[(size_t)n * 288 + idx] = kg[hh * 36 + 12 + rem];
    }
    if (t < 12) {
        int hh = t; float hw = hw_s[hh];
        float Sk = 0.f, Sq = 0.f;
        float* ke = &kext[((size_t)hh * 512 + n) * 32];
        float* qe = &qext[((size_t)n * 12 + hh) * 32];
        #pragma unroll
        for (int u = 0; u < 12; u++) {
            float kvv = kg[hh * 36 + u];  Sk += kvv * kvv;  ke[16 + u] = kvv;
            float qvv = qg[hh * 12 + u];  Sq += qvv * qvv;  qe[16 + u] = hw * qvv;
        }
        ke[28] = -0.5f * hw * Sk; ke[29] = 1.f; ke[30] = 0.f; ke[31] = 0.f;
        qe[28] = 1.f; qe[29] = -0.5f * hw * Sq; qe[30] = 0.f; qe[31] = 0.f;
    }
}

// ================= bproj2 =================
__global__ void bproj2(const float* __restrict__ z,
                       const float* __restrict__ Wb,
                       const float* __restrict__ bb,
                       float* __restrict__ bmat) {
    extern __shared__ float zs[];           // [256][132]
    __shared__ float Wb_s[128 * 12];
    __shared__ float bb_s[12];
    const float c_b = 0.5773502691896258f;
    int t = threadIdx.x;                    // 256
    size_t r0 = (size_t)blockIdx.x * 256;
    for (int idx = t; idx < 1536; idx += 256) Wb_s[idx] = c_b * Wb[idx];
    if (t < 12) bb_s[t] = c_b * bb[t];
    for (int idx = t; idx < 8192; idx += 256) {
        int row = idx >> 5, c4 = (idx & 31) << 2;
        float4 vv = *(const float4*)&z[(r0 + row) * 128 + c4];
        *(float4*)&zs[row * 132 + c4] = vv;
    }
    __syncthreads();
    int rg = t >> 2, hg = (t & 3) * 3;
    float acc[4][3] = {};
    #pragma unroll 2
    for (int d = 0; d < 128; d++) {
        float w0 = Wb_s[d * 12 + hg];
        float w1 = Wb_s[d * 12 + hg + 1];
        float w2 = Wb_s[d * 12 + hg + 2];
        #pragma unroll
        for (int rr = 0; rr < 4; rr++) {
            float zv = zs[(rg + 64 * rr) * 132 + d];
            acc[rr][0] += zv * w0;
            acc[rr][1] += zv * w1;
            acc[rr][2] += zv * w2;
        }
    }
    int i = (int)(r0 >> 9);
    int jbase = (int)(r0 & 511);
    #pragma unroll
    for (int rr = 0; rr < 4; rr++) {
        int j = jbase + rg + 64 * rr;
        #pragma unroll
        for (int hh = 0; hh < 3; hh++)
            bmat[((size_t)i * 12 + hg + hh) * 512 + j] = acc[rr][hh] + bb_s[hg + hh];
    }
}

// ================= logits (rank-30 GEMM) + mask + softmax =================
__global__ void logits_softmax(const float* __restrict__ qext,
                               const float* __restrict__ kext,
                               const float* __restrict__ bmat,
                               const float* __restrict__ mask,
                               float* __restrict__ a) {
    int i0 = blockIdx.x * 32, h = blockIdx.y;
    int t = threadIdx.x;     // 256
    int w = t >> 5, l = t & 31;
    __shared__ __align__(16) float qe[32][32];
    __shared__ __align__(16) float ke[32][65];
    __shared__ __align__(16) float b_s[32][64];
    __shared__ float ms[512], mi_s[32];
    {
        int r = t >> 3, d4 = (t & 7) << 2;
        *(float4*)&qe[r][d4] = *(const float4*)&qext[((size_t)(i0 + r) * 12 + h) * 32 + d4];
    }
    for (int idx = t; idx < 512; idx += 256) ms[idx] = mask[idx];
    if (t < 32) mi_s[t] = mask[i0 + t];
    float rmax[4] = {-3.4e38f, -3.4e38f, -3.4e38f, -3.4e38f};
    for (int jt = 0; jt < 8; jt++) {
        int j0 = jt * 64;
        __syncthreads();
        #pragma unroll
        for (int idx = t; idx < 512; idx += 256) {
            int jr = idx >> 3, d4 = (idx & 7) << 2;
            float4 kv = *(const float4*)&kext[((size_t)h * 512 + j0 + jr) * 32 + d4];
            ke[d4 + 0][jr] = kv.x; ke[d4 + 1][jr] = kv.y;
            ke[d4 + 2][jr] = kv.z; ke[d4 + 3][jr] = kv.w;
        }
        #pragma unroll
        for (int idx = t; idx < 512; idx += 256) {
            int r = idx >> 4, c4 = (idx & 15) << 2;
            *(float4*)&b_s[r][c4] =
                *(const float4*)&bmat[((size_t)(i0 + r) * 12 + h) * 512 + j0 + c4];
        }
        __syncthreads();
        float acc[4][2] = {};
        #pragma unroll 4
        for (int d = 0; d < 30; d++) {
            float k0 = ke[d][l], k1 = ke[d][l + 32];
            #pragma unroll
            for (int rr = 0; rr < 4; rr++) {
                float qv = qe[(w << 2) + rr][d];
                acc[rr][0] += qv * k0;
                acc[rr][1] += qv * k1;
            }
        }
        float mj0 = ms[j0 + l], mj1 = ms[j0 + l + 32];
        #pragma unroll
        for (int rr = 0; rr < 4; rr++) {
            int r = (w << 2) + rr;
            float mi = mi_s[r];
            float lg0 = acc[rr][0] + b_s[r][l]      + INF_ * fmaf(mi, mj0, -1.f);
            float lg1 = acc[rr][1] + b_s[r][l + 32] + INF_ * fmaf(mi, mj1, -1.f);
            float* arow = a + ((size_t)(i0 + r) * 12 + h) * 512 + j0;
            arow[l] = lg0;
            arow[l + 32] = lg1;
            rmax[rr] = fmaxf(rmax[rr], fmaxf(lg0, lg1));
        }
    }
    __syncthreads();
    #pragma unroll
    for (int off = 16; off > 0; off >>= 1)
        #pragma unroll
        for (int rr = 0; rr < 4; rr++)
            rmax[rr] = fmaxf(rmax[rr], __shfl_xor_sync(0xffffffffu, rmax[rr], off));
    #pragma unroll
    for (int rr = 0; rr < 4; rr++) {
        float* arow = a + ((size_t)(i0 + (w << 2) + rr) * 12 + h) * 512;
        float mx = rmax[rr];
        float sum = 0.f;
        #pragma unroll
        for (int c = l; c < 512; c += 32) sum += __expf(arow[c] - mx);
        #pragma unroll
        for (int off = 16; off > 0; off >>= 1)
            sum += __shfl_xor_sync(0xffffffffu, sum, off);
        float inv = 1.f / sum;
        #pragma unroll
        for (int c = l; c < 512; c += 32) arow[c] = __expf(arow[c] - mx) * inv;
    }
}

// ================= att_out =================
__global__ void att_out(const float* __restrict__ a,
                        const float* __restrict__ v,
                        const float* __restrict__ vpts,
                        const float* __restrict__ rot,
                        const float* __restrict__ trans,
                        float* __restrict__ cat) {
    int i0 = blockIdx.x * 4;
    int t = threadIdx.x;    // 480
    __shared__ float a_s[4][768];
    __shared__ float opts[4][288];
    __shared__ float Rs[4][9], ts[4][3];
    if (t < 36) Rs[t / 9][t % 9] = rot[(i0 + t / 9) * 9 + t % 9];
    if (t >= 64 && t < 76) {
        int r = (t - 64) / 3, cpt = (t - 64) % 3;
        ts[r][cpt] = trans[(i0 + r) * 3 + cpt];
    }
    float acc[4] = {0.f, 0.f, 0.f, 0.f};
    int h = (t < 192) ? (t >> 4) : ((t - 192) / 24);
    const float* src = (t < 192) ? (v + t) : (vpts + (t - 192));
    int stride = (t < 192) ? 192 : 288;
    for (int j0 = 0; j0 < 512; j0 += 64) {
        for (int idx = t; idx < 3072; idx += 480) {
            int r = idx / 768;
            int rem = idx - r * 768;
            int hh = rem >> 6, jj = rem & 63;
            a_s[r][rem] = a[((size_t)(i0 + r) * 12 + hh) * 512 + j0 + jj];
        }
        __syncthreads();
        const float* sp = src + (size_t)j0 * stride;
        const float* as0 = &a_s[0][h * 64];
        #pragma unroll 4
        for (int jj = 0; jj < 64; jj++) {
            float val = sp[(size_t)jj * stride];
            acc[0] += as0[jj]        * val;
            acc[1] += as0[768 + jj]  * val;
            acc[2] += as0[1536 + jj] * val;
            acc[3] += as0[2304 + jj] * val;
        }
        __syncthreads();
    }
    if (t >= 192) {
        #pragma unroll
        for (int r = 0; r < 4; r++) opts[r][t - 192] = acc[r];
    }
    __syncthreads();
    #pragma unroll
    for (int r = 0; r < 4; r++) {
        float* crow = cat + (size_t)(i0 + r) * 2112;
        if (t < 192) crow[t] = acc[r];
        if (t < 96) {
            int hh = t >> 3, p = t & 7;
            int base = hh * 24 + p * 3;
            float gx = opts[r][base]     - ts[r][0];
            float gy = opts[r][base + 1] - ts[r][1];
            float gz = opts[r][base + 2] - ts[r][2];
            float lx = Rs[r][0] * gx + Rs[r][3] * gy + Rs[r][6] * gz;
            float ly = Rs[r][1] * gx + Rs[r][4] * gy + Rs[r][7] * gz;
            float lz = Rs[r][2] * gx + Rs[r][5] * gy + Rs[r][8] * gz;
            crow[192 + t] = lx;
            crow[288 + t] = ly;
            crow[384 + t] = lz;
            crow[480 + t] = sqrtf(lx * lx + ly * ly + lz * lz + 1e-8f);
        }
    }
}

// ================= opair =================
__global__ void opair(const float* __restrict__ a,
                      const float* __restrict__ z,
                      float* __restrict__ cat) {
    int i = blockIdx.x;
    int c = threadIdx.x;   // 128
    __shared__ __align__(16) float a_s[768];
    float acc[12] = {};
    for (int j0 = 0; j0 < 512; j0 += 64) {
        for (int idx = c; idx < 768; idx += 128) {
            int hh = idx >> 6, jj = idx & 63;
            a_s[idx] = a[((size_t)i * 12 + hh) * 512 + j0 + jj];
        }
        __syncthreads();
        const float* zp = z + ((size_t)i * 512 + j0) * 128 + c;
        #pragma unroll
        for (int jj4 = 0; jj4 < 16; jj4++) {
            int jj = jj4 * 4;
            float z0 = zp[(size_t)(jj + 0) * 128];
            float z1 = zp[(size_t)(jj + 1) * 128];
            float z2 = zp[(size_t)(jj + 2) * 128];
            float z3 = zp[(size_t)(jj + 3) * 128];
            #pragma unroll
            for (int hh = 0; hh < 12; hh++) {
                float4 av = *(const float4*)&a_s[hh * 64 + jj];
                acc[hh] += av.x * z0 + av.y * z1 + av.z * z2 + av.w * z3;
            }
        }
        __syncthreads();
    }
    float* crow = cat + (size_t)i * 2112 + 576;
    #pragma unroll
    for (int hh = 0; hh < 12; hh++)
        crow[hh * 128 + c] = acc[hh];
}

// ================= launch =================
extern "C" void kernel_launch(void* const* d_in, const int* in_sizes, int n_in,
                              void* d_out, int out_size) {
    const float* s      = (const float*)d_in[0];
    const float* z      = (const float*)d_in[1];
    const float* rot    = (const float*)d_in[2];
    const float* trans  = (const float*)d_in[3];
    const float* mask   = (const float*)d_in[4];
    const float* Wq     = (const float*)d_in[5];
    const float* bq     = (const float*)d_in[6];
    const float* Wkv    = (const float*)d_in[7];
    const float* bkv    = (const float*)d_in[8];
    const float* Wqp    = (const float*)d_in[9];
    const float* bqp    = (const float*)d_in[10];
    const float* Wkvp   = (const float*)d_in[11];
    const float* bkvp   = (const float*)d_in[12];
    const float* Wb     = (const float*)d_in[13];
    const float* bb     = (const float*)d_in[14];
    const float* head_w = (const float*)d_in[15];
    const float* Wout   = (const float*)d_in[16];
    const float* bout   = (const float*)d_in[17];
    float* out = (float*)d_out;

    float* base = nullptr;
    cudaGetSymbolAddress((void**)&base, g_scratch);
    float* proj  = base + OFF_PROJ;
    float* kext  = base + OFF_KEXT;
    float* qext  = base + OFF_QEXT;
    float* v     = base + OFF_V;
    float* vpts  = base + OFF_VPTS;
    float* bmat  = base + OFF_B;
    float* amat  = base + OFF_A;
    float* cat   = base + OFF_CAT;
    __nv_bfloat16* Aint  = (__nv_bfloat16*)(base + OFF_AINT);
    __nv_bfloat16* WintP = (__nv_bfloat16*)(base + OFF_WINTP);
    __nv_bfloat16* Cint  = (__nv_bfloat16*)(base + OFF_CINT);
    __nv_bfloat16* WintO = (__nv_bfloat16*)(base + OFF_WINTO);
    float* biasA = base + OFF_BIASA;

    static int attr_set = 0;
    if (!attr_set) {
        cudaFuncSetAttribute(bproj2, cudaFuncAttributeMaxDynamicSharedMemorySize,
                             256 * 132 * 4);
        attr_set = 1;
    }

    // split inputs + weights to interleaved bf16 hi/lo
    split_rows<<<512, 512>>>(s, Aint, 1024);
    split_w<<<dim3(512, 1), 256>>>(Wq,   WintP, 192, 3072, 0);
    split_w<<<dim3(512, 2), 256>>>(Wkv,  WintP, 384, 3072, 192);
    split_w<<<dim3(512, 1), 256>>>(Wqp,  WintP, 144, 3072, 576);
    split_w<<<dim3(512, 2), 256>>>(Wkvp, WintP, 432, 3072, 720);
    concat_bias<<<5, 256>>>(bq, bkv, bqp, bkvp, biasA);

    // fused projection GEMM: [512,1152] = s @ [Wq|Wkv|Wqp|Wkvp]
    mma_gemm<<<dim3(18, 8), 128>>>(Aint, WintP, biasA, proj, 3072, 1152);

    pointify<<<512, 256>>>(proj, rot, trans, head_w, kext, qext, v, vpts);
    bproj2<<<1024, 256, 256 * 132 * 4>>>(z, Wb, bb, bmat);
    logits_softmax<<<dim3(16, 12), 256>>>(qext, kext, bmat, mask, amat);
    att_out<<<128, 480>>>(amat, v, vpts, rot, trans, cat);
    opair<<<512, 128>>>(amat, z, cat);

    // output GEMM: [512,1024] = cat @ Wout
    split_rows<<<512, 512>>>(cat, Cint, 2112);
    split_w<<<dim3(1056, 4), 256>>>(Wout, WintO, 1024, 6336, 0);
    mma_gemm<<<dim3(16, 8), 128>>>(Cint, WintO, bout, out, 6336, 1024);
}

// round 8
// speedup vs baseline: 1.9909x; 1.0094x over previous
#include <cuda_runtime.h>
#include <cuda_bf16.h>
#include <math.h>
#include <stdint.h>

#define INF_ 100000.0f

// ================= scratch (floats) =================
static constexpr size_t OFF_PROJ  = 0;                                 // 512*1152
static constexpr size_t OFF_KEXT  = OFF_PROJ  + (size_t)512*1152;      // 12*512*32
static constexpr size_t OFF_QEXT  = OFF_KEXT  + (size_t)12*512*32;     // 512*12*32
static constexpr size_t OFF_V     = OFF_QEXT  + (size_t)512*12*32;     // 512*192
static constexpr size_t OFF_VPTS  = OFF_V     + (size_t)512*192;       // 512*288
static constexpr size_t OFF_B     = OFF_VPTS  + (size_t)512*288;       // 512*12*512
static constexpr size_t OFF_A     = OFF_B     + (size_t)512*12*512;    // 512*12*512
static constexpr size_t OFF_AINT  = OFF_A     + (size_t)512*12*512;    // bf16 512*3072
static constexpr size_t OFF_WINTP = OFF_AINT  + (size_t)512*3072/2;    // bf16 1152*3072
static constexpr size_t OFF_CINT  = OFF_WINTP + (size_t)1152*3072/2;   // bf16 512*6336
static constexpr size_t OFF_WINTO = OFF_CINT  + (size_t)512*6336/2;    // bf16 1024*6336
static constexpr size_t OFF_BIASA = OFF_WINTO + (size_t)1024*6336/2;   // 1152
static constexpr size_t SCRATCH_TOTAL = OFF_BIASA + 1152;

__device__ __align__(256) float g_scratch[SCRATCH_TOTAL];

__device__ __forceinline__ uint32_t smem_u32(const void* p) {
    uint32_t a;
    asm("{ .reg .u64 t; cvta.to.shared.u64 t, %1; cvt.u32.u64 %0, t; }" : "=r"(a) : "l"(p));
    return a;
}

// write one fp32 pair as the 3-u32 interleaved hi/lo pattern (A-side: [hi,lo][hi,hi][lo,hi])
__device__ __forceinline__ void bf16pair_store(uint32_t* d, int p, float a0, float a1) {
    __nv_bfloat16 h0 = __float2bfloat16(a0);
    __nv_bfloat16 l0 = __float2bfloat16(a0 - __bfloat162float(h0));
    __nv_bfloat16 h1 = __float2bfloat16(a1);
    __nv_bfloat16 l1 = __float2bfloat16(a1 - __bfloat162float(h1));
    uint32_t uh0 = __bfloat16_as_ushort(h0), ul0 = __bfloat16_as_ushort(l0);
    uint32_t uh1 = __bfloat16_as_ushort(h1), ul1 = __bfloat16_as_ushort(l1);
    d[3 * p + 0] = uh0 | (ul0 << 16);
    d[3 * p + 1] = uh0 | (uh1 << 16);
    d[3 * p + 2] = ul1 | (uh1 << 16);
}

// ================= prep_all: every input-side split in ONE launch =================
__device__ __forceinline__ void wsplit_body(const float* __restrict__ W,
                                            __nv_bfloat16* __restrict__ dst,
                                            int N, int Kp, int rowoff, int kp, int n) {
    if (n >= N) return;
    float a0 = W[(size_t)(2 * kp) * N + n];
    float a1 = W[(size_t)(2 * kp + 1) * N + n];
    __nv_bfloat16 h0 = __float2bfloat16(a0);
    __nv_bfloat16 l0 = __float2bfloat16(a0 - __bfloat162float(h0));
    __nv_bfloat16 h1 = __float2bfloat16(a1);
    __nv_bfloat16 l1 = __float2bfloat16(a1 - __bfloat162float(h1));
    uint32_t uh0 = __bfloat16_as_ushort(h0), ul0 = __bfloat16_as_ushort(l0);
    uint32_t uh1 = __bfloat16_as_ushort(h1), ul1 = __bfloat16_as_ushort(l1);
    uint32_t* d = (uint32_t*)(dst + (size_t)(rowoff + n) * Kp) + 3 * kp;
    d[0] = uh0 | (uh0 << 16);   // W-side: [hi,hi][lo,hi][hi,lo]
    d[1] = ul0 | (uh1 << 16);
    d[2] = uh1 | (ul1 << 16);
}

__global__ void prep_all(const float* __restrict__ s,
                         const float* __restrict__ Wq,  const float* __restrict__ Wkv,
                         const float* __restrict__ Wqp, const float* __restrict__ Wkvp,
                         const float* __restrict__ Wout,
                         const float* __restrict__ bq,  const float* __restrict__ bkv,
                         const float* __restrict__ bqp, const float* __restrict__ bkvp,
                         __nv_bfloat16* __restrict__ Aint,
                         __nv_bfloat16* __restrict__ WintP,
                         __nv_bfloat16* __restrict__ WintO,
                         float* __restrict__ biasA) {
    int bid = blockIdx.x, t = threadIdx.x;     // 256 threads
    if (bid < 512) {                            // split s rows (K=1024)
        const float* sr = s + (size_t)bid * 1024;
        uint32_t* d = (uint32_t*)(Aint + (size_t)bid * 3072);
        #pragma unroll
        for (int u = 0; u < 2; u++) {
            int p = t + u * 256;
            float a0 = sr[2 * p], a1 = sr[2 * p + 1];
            __nv_bfloat16 h0 = __float2bfloat16(a0);
            __nv_bfloat16 l0 = __float2bfloat16(a0 - __bfloat162float(h0));
            __nv_bfloat16 h1 = __float2bfloat16(a1);
            __nv_bfloat16 l1 = __float2bfloat16(a1 - __bfloat162float(h1));
            uint32_t uh0 = __bfloat16_as_ushort(h0), ul0 = __bfloat16_as_ushort(l0);
            uint32_t uh1 = __bfloat16_as_ushort(h1), ul1 = __bfloat16_as_ushort(l1);
            d[3 * p + 0] = uh0 | (ul0 << 16);
            d[3 * p + 1] = uh0 | (uh1 << 16);
            d[3 * p + 2] = ul1 | (uh1 << 16);
        }
    } else if (bid < 1024) {
        wsplit_body(Wq, WintP, 192, 3072, 0, bid - 512, t);
    } else if (bid < 2048) {
        int local = bid - 1024;
        wsplit_body(Wkv, WintP, 384, 3072, 192, local >> 1, ((local & 1) << 8) + t);
    } else if (bid < 2560) {
        wsplit_body(Wqp, WintP, 144, 3072, 576, bid - 2048, t);
    } else if (bid < 3584) {
        int local = bid - 2560;
        wsplit_body(Wkvp, WintP, 432, 3072, 720, local >> 1, ((local & 1) << 8) + t);
    } else if (bid < 7808) {
        int local = bid - 3584;
        wsplit_body(Wout, WintO, 1024, 6336, 0, local >> 2, ((local & 3) << 8) + t);
    } else {
        int idx = (bid - 7808) * 256 + t;
        if (idx < 1152) {
            float v;
            if (idx < 192) v = bq[idx];
            else if (idx < 576) v = bkv[idx - 192];
            else if (idx < 720) v = bqp[idx - 576];
            else v = bkvp[idx - 720];
            biasA[idx] = v;
        }
    }
}

// ================= warp-MMA bf16 GEMM: 256 thr, 64x64 tile, 8 warps (16x32 each) =================
#define ROWP 72
#define BUFB (64 * ROWP * 2)

__global__ void __launch_bounds__(256) mma_gemm(const __nv_bfloat16* __restrict__ A,
                                                const __nv_bfloat16* __restrict__ B,
                                                const float* __restrict__ bias,
                                                float* __restrict__ C,
                                                int Kp, int Nld) {
    __shared__ __align__(16) __nv_bfloat16 sA[2][64][ROWP];
    __shared__ __align__(16) __nv_bfloat16 sB[2][64][ROWP];
    int tid = threadIdx.x, wid = tid >> 5, lane = tid & 31;
    int m0 = blockIdx.y * 64, n0 = blockIdx.x * 64;
    int Mw = (wid >> 1) * 16, Nw = (wid & 1) * 32;

    uint32_t sA_base = smem_u32(&sA[0][0][0]);
    uint32_t sB_base = smem_u32(&sB[0][0][0]);
    uint32_t aoff0 = ((uint32_t)((Mw + (lane & 15)) * ROWP + ((lane >> 4) << 3))) << 1;
    uint32_t boff0 = ((uint32_t)((Nw + (lane & 7)) * ROWP + (lane & 8))) << 1;

    const char* Abase = (const char*)A;
    const char* Bbase = (const char*)B;
    int ntiles = Kp >> 6;

    #pragma unroll
    for (int u = 0; u < 2; u++) {
        int idx = tid + u * 256;
        int row = idx >> 3, c = idx & 7;
        *(uint4*)((char*)&sA[0][0][0] + row * (ROWP * 2) + c * 16) =
            *(const uint4*)(Abase + ((size_t)(m0 + row) * Kp + c * 8) * 2);
        *(uint4*)((char*)&sB[0][0][0] + row * (ROWP * 2) + c * 16) =
            *(const uint4*)(Bbase + ((size_t)(n0 + row) * Kp + c * 8) * 2);
    }
    __syncthreads();

    float acc[4][4] = {};
    for (int t = 0; t < ntiles; t++) {
        int b = t & 1;
        uint4 pa[2], pb[2];
        bool more = (t + 1) < ntiles;
        if (more) {
            #pragma unroll
            for (int u = 0; u < 2; u++) {
                int idx = tid + u * 256;
                int row = idx >> 3, c = idx & 7;
                pa[u] = *(const uint4*)(Abase + ((size_t)(m0 + row) * Kp + (t + 1) * 64 + c * 8) * 2);
                pb[u] = *(const uint4*)(Bbase + ((size_t)(n0 + row) * Kp + (t + 1) * 64 + c * 8) * 2);
            }
        }
        #pragma unroll
        for (int ks = 0; ks < 4; ks++) {
            uint32_t kb = (uint32_t)ks << 5;
            uint32_t af[4], bfr[4][2];
            {
                uint32_t ad = sA_base + b * BUFB + aoff0 + kb;
                asm volatile("ldmatrix.sync.aligned.m8n8.x4.shared.b16 {%0,%1,%2,%3}, [%4];"
                    : "=r"(af[0]), "=r"(af[1]), "=r"(af[2]), "=r"(af[3]) : "r"(ad));
            }
            #pragma unroll
            for (int nt = 0; nt < 4; nt++) {
                uint32_t bd = sB_base + b * BUFB + boff0 + nt * (8 * ROWP * 2) + kb;
                asm volatile("ldmatrix.sync.aligned.m8n8.x2.shared.b16 {%0,%1}, [%2];"
                    : "=r"(bfr[nt][0]), "=r"(bfr[nt][1]) : "r"(bd));
            }
            #pragma unroll
            for (int nt = 0; nt < 4; nt++)
                asm volatile("mma.sync.aligned.m16n8k16.row.col.f32.bf16.bf16.f32 "
                    "{%0,%1,%2,%3}, {%4,%5,%6,%7}, {%8,%9}, {%0,%1,%2,%3};"
                    : "+f"(acc[nt][0]), "+f"(acc[nt][1]), "+f"(acc[nt][2]), "+f"(acc[nt][3])
                    : "r"(af[0]), "r"(af[1]), "r"(af[2]), "r"(af[3]),
                      "r"(bfr[nt][0]), "r"(bfr[nt][1]));
        }
        if (more) {
            __syncthreads();
            #pragma unroll
            for (int u = 0; u < 2; u++) {
                int idx = tid + u * 256;
                int row = idx >> 3, c = idx & 7;
                *(uint4*)((char*)&sA[b ^ 1][0][0] + row * (ROWP * 2) + c * 16) = pa[u];
                *(uint4*)((char*)&sB[b ^ 1][0][0] + row * (ROWP * 2) + c * 16) = pb[u];
            }
            __syncthreads();
        }
    }

    int r = m0 + Mw + (lane >> 2);
    #pragma unroll
    for (int nt = 0; nt < 4; nt++) {
        int col = n0 + Nw + nt * 8 + ((lane & 3) << 1);
        float b0v = bias[col], b1v = bias[col + 1];
        float2 o0 = { acc[nt][0] + b0v, acc[nt][1] + b1v };
        float2 o1 = { acc[nt][2] + b0v, acc[nt][3] + b1v };
        *(float2*)&C[(size_t)r * Nld + col] = o0;
        *(float2*)&C[(size_t)(r + 8) * Nld + col] = o1;
    }
}

// ================= pointify =================
__global__ void pointify(const float* __restrict__ proj,
                         const float* __restrict__ rot,
                         const float* __restrict__ trans,
                         const float* __restrict__ head_w,
                         float* __restrict__ kext, float* __restrict__ qext,
                         float* __restrict__ v, float* __restrict__ vpts) {
    int n = blockIdx.x, t = threadIdx.x;   // 256 threads
    __shared__ float Rs[9], ts[3], qg[144], kg[432], hw_s[12];
    const float* prow = proj + (size_t)n * 1152;
    if (t < 9) Rs[t] = rot[n * 9 + t];
    if (t >= 16 && t < 19) ts[t - 16] = trans[n * 3 + (t - 16)];
    if (t >= 32 && t < 44) {
        float w = head_w[t - 32];
        float sp = (w > 20.f) ? w : log1pf(expf(w));
        hw_s[t - 32] = sp * 0.13608276348795434f;   // sqrt(1/54)
    }
    __syncthreads();
    if (t < 48) {
        float x  = prow[576 + t];
        float y  = prow[576 + 48 + t];
        float zc = prow[576 + 96 + t];
        qg[t * 3 + 0] = Rs[0] * x + Rs[1] * y + Rs[2] * zc + ts[0];
        qg[t * 3 + 1] = Rs[3] * x + Rs[4] * y + Rs[5] * zc + ts[1];
        qg[t * 3 + 2] = Rs[6] * x + Rs[7] * y + Rs[8] * zc + ts[2];
    }
    if (t >= 64 && t < 208) {
        int pf = t - 64;
        float x  = prow[720 + pf];
        float y  = prow[720 + 144 + pf];
        float zc = prow[720 + 288 + pf];
        kg[pf * 3 + 0] = Rs[0] * x + Rs[1] * y + Rs[2] * zc + ts[0];
        kg[pf * 3 + 1] = Rs[3] * x + Rs[4] * y + Rs[5] * zc + ts[1];
        kg[pf * 3 + 2] = Rs[6] * x + Rs[7] * y + Rs[8] * zc + ts[2];
    }
    __syncthreads();
    if (t < 192) {
        int hh = t >> 4, d = t & 15;
        kext[((size_t)hh * 512 + n) * 32 + d] = prow[192 + hh * 32 + d];
        v[(size_t)n * 192 + t]                = prow[192 + hh * 32 + 16 + d];
        qext[((size_t)n * 12 + hh) * 32 + d]  = 0.14433756729740643f * prow[t];
    }
    for (int idx = t; idx < 288; idx += 256) {
        int hh = idx / 24, rem = idx % 24;
        vpts[(size_t)n * 288 + idx] = kg[hh * 36 + 12 + rem];
    }
    if (t < 12) {
        int hh = t; float hw = hw_s[hh];
        float Sk = 0.f, Sq = 0.f;
        float* ke = &kext[((size_t)hh * 512 + n) * 32];
        float* qe = &qext[((size_t)n * 12 + hh) * 32];
        #pragma unroll
        for (int u = 0; u < 12; u++) {
            float kvv = kg[hh * 36 + u];  Sk += kvv * kvv;  ke[16 + u] = kvv;
            float qvv = qg[hh * 12 + u];  Sq += qvv * qvv;  qe[16 + u] = hw * qvv;
        }
        ke[28] = -0.5f * hw * Sk; ke[29] = 1.f; ke[30] = 0.f; ke[31] = 0.f;
        qe[28] = 1.f; qe[29] = -0.5f * hw * Sq; qe[30] = 0.f; qe[31] = 0.f;
    }
}

// ================= bproj: 64-row tiles, 5 blocks/SM =================
__global__ void bproj64(const float* __restrict__ z,
                        const float* __restrict__ Wb,
                        const float* __restrict__ bb,
                        float* __restrict__ bmat) {
    __shared__ float zs[64 * 132];
    __shared__ float Wb_s[128 * 12];
    __shared__ float bb_s[12];
    const float c_b = 0.5773502691896258f;
    int t = threadIdx.x;                    // 256
    size_t r0 = (size_t)blockIdx.x * 64;
    for (int idx = t; idx < 1536; idx += 256) Wb_s[idx] = c_b * Wb[idx];
    if (t < 12) bb_s[t] = c_b * bb[t];
    #pragma unroll
    for (int u = 0; u < 8; u++) {
        int idx = t + u * 256;
        int row = idx >> 5, c4 = (idx & 31) << 2;
        float4 vv = *(const float4*)&z[(r0 + row) * 128 + c4];
        *(float4*)&zs[row * 132 + c4] = vv;
    }
    __syncthreads();
    int rg = t >> 2, hg = (t & 3) * 3;
    float acc0 = 0.f, acc1 = 0.f, acc2 = 0.f;
    #pragma unroll 4
    for (int d = 0; d < 128; d++) {
        float zv = zs[rg * 132 + d];
        acc0 += zv * Wb_s[d * 12 + hg];
        acc1 += zv * Wb_s[d * 12 + hg + 1];
        acc2 += zv * Wb_s[d * 12 + hg + 2];
    }
    size_t row = r0 + rg;
    int i = (int)(row >> 9), j = (int)(row & 511);
    bmat[((size_t)i * 12 + hg + 0) * 512 + j] = acc0 + bb_s[hg + 0];
    bmat[((size_t)i * 12 + hg + 1) * 512 + j] = acc1 + bb_s[hg + 1];
    bmat[((size_t)i * 12 + hg + 2) * 512 + j] = acc2 + bb_s[hg + 2];
}

// ================= logits (rank-30) + mask + softmax, 16 rows/block =================
__global__ void logits_softmax(const float* __restrict__ qext,
                               const float* __restrict__ kext,
                               const float* __restrict__ bmat,
                               const float* __restrict__ mask,
                               float* __restrict__ a) {
    int i0 = blockIdx.x * 16, h = blockIdx.y;   // grid (32, 12)
    int t = threadIdx.x;     // 256
    int w = t >> 5, l = t & 31;
    __shared__ __align__(16) float qe[16][32];
    __shared__ __align__(16) float ke[32][65];
    __shared__ __align__(16) float b_s[16][64];
    __shared__ float ms[512], mi_s[16];
    if (t < 128) {
        int r = t >> 3, d4 = (t & 7) << 2;
        *(float4*)&qe[r][d4] = *(const float4*)&qext[((size_t)(i0 + r) * 12 + h) * 32 + d4];
    }
    for (int idx = t; idx < 512; idx += 256) ms[idx] = mask[idx];
    if (t < 16) mi_s[t] = mask[i0 + t];
    float rmax[2] = {-3.4e38f, -3.4e38f};
    for (int jt = 0; jt < 8; jt++) {
        int j0 = jt * 64;
        __syncthreads();
        #pragma unroll
        for (int idx = t; idx < 512; idx += 256) {
            int jr = idx >> 3, d4 = (idx & 7) << 2;
            float4 kv = *(const float4*)&kext[((size_t)h * 512 + j0 + jr) * 32 + d4];
            ke[d4 + 0][jr] = kv.x; ke[d4 + 1][jr] = kv.y;
            ke[d4 + 2][jr] = kv.z; ke[d4 + 3][jr] = kv.w;
        }
        {
            int r = t >> 4, c4 = (t & 15) << 2;
            *(float4*)&b_s[r][c4] =
                *(const float4*)&bmat[((size_t)(i0 + r) * 12 + h) * 512 + j0 + c4];
        }
        __syncthreads();
        float acc[2][2] = {};
        #pragma unroll 5
        for (int d = 0; d < 30; d++) {
            float k0 = ke[d][l], k1 = ke[d][l + 32];
            #pragma unroll
            for (int rr = 0; rr < 2; rr++) {
                float qv = qe[(w << 1) + rr][d];
                acc[rr][0] += qv * k0;
                acc[rr][1] += qv * k1;
            }
        }
        float mj0 = ms[j0 + l], mj1 = ms[j0 + l + 32];
        #pragma unroll
        for (int rr = 0; rr < 2; rr++) {
            int r = (w << 1) + rr;
            float mi = mi_s[r];
            float lg0 = acc[rr][0] + b_s[r][l]      + INF_ * fmaf(mi, mj0, -1.f);
            float lg1 = acc[rr][1] + b_s[r][l + 32] + INF_ * fmaf(mi, mj1, -1.f);
            float* arow = a + ((size_t)(i0 + r) * 12 + h) * 512 + j0;
            arow[l] = lg0;
            arow[l + 32] = lg1;
            rmax[rr] = fmaxf(rmax[rr], fmaxf(lg0, lg1));
        }
    }
    #pragma unroll
    for (int off = 16; off > 0; off >>= 1)
        #pragma unroll
        for (int rr = 0; rr < 2; rr++)
            rmax[rr] = fmaxf(rmax[rr], __shfl_xor_sync(0xffffffffu, rmax[rr], off));
    #pragma unroll
    for (int rr = 0; rr < 2; rr++) {
        float* arow = a + ((size_t)(i0 + (w << 1) + rr) * 12 + h) * 512;
        float mx = rmax[rr];
        float sum = 0.f;
        #pragma unroll
        for (int c = l; c < 512; c += 32) sum += __expf(arow[c] - mx);
        #pragma unroll
        for (int off = 16; off > 0; off >>= 1)
            sum += __shfl_xor_sync(0xffffffffu, sum, off);
        float inv = 1.f / sum;
        #pragma unroll
        for (int c = l; c < 512; c += 32) arow[c] = __expf(arow[c] - mx) * inv;
    }
}

// ================= att_out -> writes bf16 triplets of cols [0,576) into Cint =================
__global__ void att_out(const float* __restrict__ a,
                        const float* __restrict__ v,
                        const float* __restrict__ vpts,
                        const float* __restrict__ rot,
                        const float* __restrict__ trans,
                        __nv_bfloat16* __restrict__ Cint) {
    int i0 = blockIdx.x * 4;
    int t = threadIdx.x;    // 480
    __shared__ float a_s[4][768];
    __shared__ float opts[4][288];
    __shared__ float cvals[4][576];
    __shared__ float Rs[4][9], ts[4][3];
    if (t < 36) Rs[t / 9][t % 9] = rot[(i0 + t / 9) * 9 + t % 9];
    if (t >= 64 && t < 76) {
        int r = (t - 64) / 3, cpt = (t - 64) % 3;
        ts[r][cpt] = trans[(i0 + r) * 3 + cpt];
    }
    float acc[4] = {0.f, 0.f, 0.f, 0.f};
    int h = (t < 192) ? (t >> 4) : ((t - 192) / 24);
    const float* src = (t < 192) ? (v + t) : (vpts + (t - 192));
    int stride = (t < 192) ? 192 : 288;
    for (int j0 = 0; j0 < 512; j0 += 64) {
        for (int idx = t; idx < 3072; idx += 480) {
            int r = idx / 768;
            int rem = idx - r * 768;
            int hh = rem >> 6, jj = rem & 63;
            a_s[r][rem] = a[((size_t)(i0 + r) * 12 + hh) * 512 + j0 + jj];
        }
        __syncthreads();
        const float* sp = src + (size_t)j0 * stride;
        const float* as0 = &a_s[0][h * 64];
        #pragma unroll 4
        for (int jj = 0; jj < 64; jj++) {
            float val = sp[(size_t)jj * stride];
            acc[0] += as0[jj]        * val;
            acc[1] += as0[768 + jj]  * val;
            acc[2] += as0[1536 + jj] * val;
            acc[3] += as0[2304 + jj] * val;
        }
        __syncthreads();
    }
    if (t >= 192) {
        #pragma unroll
        for (int r = 0; r < 4; r++) opts[r][t - 192] = acc[r];
    }
    __syncthreads();
    #pragma unroll
    for (int r = 0; r < 4; r++) {
        if (t < 192) cvals[r][t] = acc[r];
        if (t < 96) {
            int hh = t >> 3, p = t & 7;
            int base = hh * 24 + p * 3;
            float gx = opts[r][base]     - ts[r][0];
            float gy = opts[r][base + 1] - ts[r][1];
            float gz = opts[r][base + 2] - ts[r][2];
            float lx = Rs[r][0] * gx + Rs[r][3] * gy + Rs[r][6] * gz;
            float ly = Rs[r][1] * gx + Rs[r][4] * gy + Rs[r][7] * gz;
            float lz = Rs[r][2] * gx + Rs[r][5] * gy + Rs[r][8] * gz;
            cvals[r][192 + t] = lx;
            cvals[r][288 + t] = ly;
            cvals[r][384 + t] = lz;
            cvals[r][480 + t] = sqrtf(lx * lx + ly * ly + lz * lz + 1e-8f);
        }
    }
    __syncthreads();
    for (int idx = t; idx < 4 * 288; idx += 480) {
        int r = idx / 288, p = idx - r * 288;
        uint32_t* d = (uint32_t*)(Cint + (size_t)(i0 + r) * 6336);
        bf16pair_store(d, p, cvals[r][2 * p], cvals[r][2 * p + 1]);
    }
}

// ================= opair -> writes bf16 triplets of cols [576,2112) into Cint =================
__global__ void opair(const float* __restrict__ a,
                      const float* __restrict__ z,
                      __nv_bfloat16* __restrict__ Cint) {
    int i = blockIdx.x;
    int c = threadIdx.x;   // 128
    __shared__ __align__(16) float a_s[768];
    float acc[12] = {};
    for (int j0 = 0; j0 < 512; j0 += 64) {
        for (int idx = c; idx < 768; idx += 128) {
            int hh = idx >> 6, jj = idx & 63;
            a_s[idx] = a[((size_t)i * 12 + hh) * 512 + j0 + jj];
        }
        __syncthreads();
        const float* zp = z + ((size_t)i * 512 + j0) * 128 + c;
        #pragma unroll
        for (int jj4 = 0; jj4 < 16; jj4++) {
            int jj = jj4 * 4;
            float z0 = zp[(size_t)(jj + 0) * 128];
            float z1 = zp[(size_t)(jj + 1) * 128];
            float z2 = zp[(size_t)(jj + 2) * 128];
            float z3 = zp[(size_t)(jj + 3) * 128];
            #pragma unroll
            for (int hh = 0; hh < 12; hh++) {
                float4 av = *(const float4*)&a_s[hh * 64 + jj];
                acc[hh] += av.x * z0 + av.y * z1 + av.z * z2 + av.w * z3;
            }
        }
        __syncthreads();
    }
    uint32_t* d = (uint32_t*)(Cint + (size_t)i * 6336);
    #pragma unroll
    for (int hh = 0; hh < 12; hh++) {
        float other = __shfl_xor_sync(0xffffffffu, acc[hh], 1);
        if (!(c & 1)) {
            int p = 288 + hh * 64 + (c >> 1);
            bf16pair_store(d, p, acc[hh], other);
        }
    }
}

// ================= launch =================
extern "C" void kernel_launch(void* const* d_in, const int* in_sizes, int n_in,
                              void* d_out, int out_size) {
    const float* s      = (const float*)d_in[0];
    const float* z      = (const float*)d_in[1];
    const float* rot    = (const float*)d_in[2];
    const float* trans  = (const float*)d_in[3];
    const float* mask   = (const float*)d_in[4];
    const float* Wq     = (const float*)d_in[5];
    const float* bq     = (const float*)d_in[6];
    const float* Wkv    = (const float*)d_in[7];
    const float* bkv    = (const float*)d_in[8];
    const float* Wqp    = (const float*)d_in[9];
    const float* bqp    = (const float*)d_in[10];
    const float* Wkvp   = (const float*)d_in[11];
    const float* bkvp   = (const float*)d_in[12];
    const float* Wb     = (const float*)d_in[13];
    const float* bb     = (const float*)d_in[14];
    const float* head_w = (const float*)d_in[15];
    const float* Wout   = (const float*)d_in[16];
    const float* bout   = (const float*)d_in[17];
    float* out = (float*)d_out;

    float* base = nullptr;
    cudaGetSymbolAddress((void**)&base, g_scratch);
    float* proj  = base + OFF_PROJ;
    float* kext  = base + OFF_KEXT;
    float* qext  = base + OFF_QEXT;
    float* v     = base + OFF_V;
    float* vpts  = base + OFF_VPTS;
    float* bmat  = base + OFF_B;
    float* amat  = base + OFF_A;
    __nv_bfloat16* Aint  = (__nv_bfloat16*)(base + OFF_AINT);
    __nv_bfloat16* WintP = (__nv_bfloat16*)(base + OFF_WINTP);
    __nv_bfloat16* Cint  = (__nv_bfloat16*)(base + OFF_CINT);
    __nv_bfloat16* WintO = (__nv_bfloat16*)(base + OFF_WINTO);
    float* biasA = base + OFF_BIASA;

    prep_all<<<7813, 256>>>(s, Wq, Wkv, Wqp, Wkvp, Wout, bq, bkv, bqp, bkvp,
                            Aint, WintP, WintO, biasA);

    // fused projection GEMM: [512,1152] = s @ [Wq|Wkv|Wqp|Wkvp]
    mma_gemm<<<dim3(18, 8), 256>>>(Aint, WintP, biasA, proj, 3072, 1152);

    pointify<<<512, 256>>>(proj, rot, trans, head_w, kext, qext, v, vpts);
    bproj64<<<4096, 256>>>(z, Wb, bb, bmat);
    logits_softmax<<<dim3(32, 12), 256>>>(qext, kext, bmat, mask, amat);
    att_out<<<128, 480>>>(amat, v, vpts, rot, trans, Cint);
    opair<<<512, 128>>>(amat, z, Cint);

    // output GEMM: [512,1024] = cat @ Wout (cat already split into Cint)
    mma_gemm<<<dim3(16, 8), 256>>>(Cint, WintO, bout, out, 6336, 1024);
}

// round 10
// speedup vs baseline: 2.1690x; 1.0895x over previous
#include <cuda_runtime.h>
#include <cuda_bf16.h>
#include <math.h>
#include <stdint.h>

#define INF_ 100000.0f

// ================= scratch (floats) =================
static constexpr size_t OFF_PROJ  = 0;                                 // 512*1152
static constexpr size_t OFF_KEXT  = OFF_PROJ  + (size_t)512*1152;      // 12*512*32
static constexpr size_t OFF_QEXT  = OFF_KEXT  + (size_t)12*512*32;     // 512*12*32
static constexpr size_t OFF_V     = OFF_QEXT  + (size_t)512*12*32;     // 512*192
static constexpr size_t OFF_VPTS  = OFF_V     + (size_t)512*192;       // 512*288
static constexpr size_t OFF_B     = OFF_VPTS  + (size_t)512*288;       // 512*12*512
static constexpr size_t OFF_A     = OFF_B     + (size_t)512*12*512;    // 512*12*512
static constexpr size_t OFF_AINT  = OFF_A     + (size_t)512*12*512;    // bf16 512*3072
static constexpr size_t OFF_WINTP = OFF_AINT  + (size_t)512*3072/2;    // bf16 1152*3072
static constexpr size_t OFF_CINT  = OFF_WINTP + (size_t)1152*3072/2;   // bf16 512*6336
static constexpr size_t OFF_WINTO = OFF_CINT  + (size_t)512*6336/2;    // bf16 1024*6336
static constexpr size_t OFF_BIASA = OFF_WINTO + (size_t)1024*6336/2;   // 1152
static constexpr size_t SCRATCH_TOTAL = OFF_BIASA + 1152;

__device__ __align__(256) float g_scratch[SCRATCH_TOTAL];

__device__ __forceinline__ uint32_t smem_u32(const void* p) {
    uint32_t a;
    asm("{ .reg .u64 t; cvta.to.shared.u64 t, %1; cvt.u32.u64 %0, t; }" : "=r"(a) : "l"(p));
    return a;
}

// write one fp32 pair as the 3-u32 interleaved hi/lo pattern (A-side: [hi,lo][hi,hi][lo,hi])
__device__ __forceinline__ void bf16pair_store(uint32_t* d, int p, float a0, float a1) {
    __nv_bfloat16 h0 = __float2bfloat16(a0);
    __nv_bfloat16 l0 = __float2bfloat16(a0 - __bfloat162float(h0));
    __nv_bfloat16 h1 = __float2bfloat16(a1);
    __nv_bfloat16 l1 = __float2bfloat16(a1 - __bfloat162float(h1));
    uint32_t uh0 = __bfloat16_as_ushort(h0), ul0 = __bfloat16_as_ushort(l0);
    uint32_t uh1 = __bfloat16_as_ushort(h1), ul1 = __bfloat16_as_ushort(l1);
    d[3 * p + 0] = uh0 | (ul0 << 16);
    d[3 * p + 1] = uh0 | (uh1 << 16);
    d[3 * p + 2] = ul1 | (uh1 << 16);
}

// ================= prep_all =================
__device__ __forceinline__ void wsplit_body(const float* __restrict__ W,
                                            __nv_bfloat16* __restrict__ dst,
                                            int N, int Kp, int rowoff, int kp, int n) {
    if (n >= N) return;
    float a0 = W[(size_t)(2 * kp) * N + n];
    float a1 = W[(size_t)(2 * kp + 1) * N + n];
    __nv_bfloat16 h0 = __float2bfloat16(a0);
    __nv_bfloat16 l0 = __float2bfloat16(a0 - __bfloat162float(h0));
    __nv_bfloat16 h1 = __float2bfloat16(a1);
    __nv_bfloat16 l1 = __float2bfloat16(a1 - __bfloat162float(h1));
    uint32_t uh0 = __bfloat16_as_ushort(h0), ul0 = __bfloat16_as_ushort(l0);
    uint32_t uh1 = __bfloat16_as_ushort(h1), ul1 = __bfloat16_as_ushort(l1);
    uint32_t* d = (uint32_t*)(dst + (size_t)(rowoff + n) * Kp) + 3 * kp;
    d[0] = uh0 | (uh0 << 16);   // W-side: [hi,hi][lo,hi][hi,lo]
    d[1] = ul0 | (uh1 << 16);
    d[2] = uh1 | (ul1 << 16);
}

__global__ void prep_all(const float* __restrict__ s,
                         const float* __restrict__ Wq,  const float* __restrict__ Wkv,
                         const float* __restrict__ Wqp, const float* __restrict__ Wkvp,
                         const float* __restrict__ Wout,
                         const float* __restrict__ bq,  const float* __restrict__ bkv,
                         const float* __restrict__ bqp, const float* __restrict__ bkvp,
                         __nv_bfloat16* __restrict__ Aint,
                         __nv_bfloat16* __restrict__ WintP,
                         __nv_bfloat16* __restrict__ WintO,
                         float* __restrict__ biasA) {
    int bid = blockIdx.x, t = threadIdx.x;     // 256 threads
    if (bid < 512) {
        const float* sr = s + (size_t)bid * 1024;
        uint32_t* d = (uint32_t*)(Aint + (size_t)bid * 3072);
        #pragma unroll
        for (int u = 0; u < 2; u++) {
            int p = t + u * 256;
            float a0 = sr[2 * p], a1 = sr[2 * p + 1];
            __nv_bfloat16 h0 = __float2bfloat16(a0);
            __nv_bfloat16 l0 = __float2bfloat16(a0 - __bfloat162float(h0));
            __nv_bfloat16 h1 = __float2bfloat16(a1);
            __nv_bfloat16 l1 = __float2bfloat16(a1 - __bfloat162float(h1));
            uint32_t uh0 = __bfloat16_as_ushort(h0), ul0 = __bfloat16_as_ushort(l0);
            uint32_t uh1 = __bfloat16_as_ushort(h1), ul1 = __bfloat16_as_ushort(l1);
            d[3 * p + 0] = uh0 | (ul0 << 16);
            d[3 * p + 1] = uh0 | (uh1 << 16);
            d[3 * p + 2] = ul1 | (uh1 << 16);
        }
    } else if (bid < 1024) {
        wsplit_body(Wq, WintP, 192, 3072, 0, bid - 512, t);
    } else if (bid < 2048) {
        int local = bid - 1024;
        wsplit_body(Wkv, WintP, 384, 3072, 192, local >> 1, ((local & 1) << 8) + t);
    } else if (bid < 2560) {
        wsplit_body(Wqp, WintP, 144, 3072, 576, bid - 2048, t);
    } else if (bid < 3584) {
        int local = bid - 2560;
        wsplit_body(Wkvp, WintP, 432, 3072, 720, local >> 1, ((local & 1) << 8) + t);
    } else if (bid < 7808) {
        int local = bid - 3584;
        wsplit_body(Wout, WintO, 1024, 6336, 0, local >> 2, ((local & 3) << 8) + t);
    } else {
        int idx = (bid - 7808) * 256 + t;
        if (idx < 1152) {
            float v;
            if (idx < 192) v = bq[idx];
            else if (idx < 576) v = bkv[idx - 192];
            else if (idx < 720) v = bqp[idx - 576];
            else v = bkvp[idx - 720];
            biasA[idx] = v;
        }
    }
}

// ================= warp-MMA bf16 GEMM: 256 thr, 64x64 tile, 8 warps (16x32 each) =================
#define ROWP 72
#define BUFB (64 * ROWP * 2)

__global__ void __launch_bounds__(256) mma_gemm(const __nv_bfloat16* __restrict__ A,
                                                const __nv_bfloat16* __restrict__ B,
                                                const float* __restrict__ bias,
                                                float* __restrict__ C,
                                                int Kp, int Nld) {
    __shared__ __align__(16) __nv_bfloat16 sA[2][64][ROWP];
    __shared__ __align__(16) __nv_bfloat16 sB[2][64][ROWP];
    int tid = threadIdx.x, wid = tid >> 5, lane = tid & 31;
    int m0 = blockIdx.y * 64, n0 = blockIdx.x * 64;
    int Mw = (wid >> 1) * 16, Nw = (wid & 1) * 32;

    uint32_t sA_base = smem_u32(&sA[0][0][0]);
    uint32_t sB_base = smem_u32(&sB[0][0][0]);
    uint32_t aoff0 = ((uint32_t)((Mw + (lane & 15)) * ROWP + ((lane >> 4) << 3))) << 1;
    uint32_t boff0 = ((uint32_t)((Nw + (lane & 7)) * ROWP + (lane & 8))) << 1;

    const char* Abase = (const char*)A;
    const char* Bbase = (const char*)B;
    int ntiles = Kp >> 6;

    #pragma unroll
    for (int u = 0; u < 2; u++) {
        int idx = tid + u * 256;
        int row = idx >> 3, c = idx & 7;
        *(uint4*)((char*)&sA[0][0][0] + row * (ROWP * 2) + c * 16) =
            *(const uint4*)(Abase + ((size_t)(m0 + row) * Kp + c * 8) * 2);
        *(uint4*)((char*)&sB[0][0][0] + row * (ROWP * 2) + c * 16) =
            *(const uint4*)(Bbase + ((size_t)(n0 + row) * Kp + c * 8) * 2);
    }
    __syncthreads();

    float acc[4][4] = {};
    for (int t = 0; t < ntiles; t++) {
        int b = t & 1;
        uint4 pa[2], pb[2];
        bool more = (t + 1) < ntiles;
        if (more) {
            #pragma unroll
            for (int u = 0; u < 2; u++) {
                int idx = tid + u * 256;
                int row = idx >> 3, c = idx & 7;
                pa[u] = *(const uint4*)(Abase + ((size_t)(m0 + row) * Kp + (t + 1) * 64 + c * 8) * 2);
                pb[u] = *(const uint4*)(Bbase + ((size_t)(n0 + row) * Kp + (t + 1) * 64 + c * 8) * 2);
            }
        }
        #pragma unroll
        for (int ks = 0; ks < 4; ks++) {
            uint32_t kb = (uint32_t)ks << 5;
            uint32_t af[4], bfr[4][2];
            {
                uint32_t ad = sA_base + b * BUFB + aoff0 + kb;
                asm volatile("ldmatrix.sync.aligned.m8n8.x4.shared.b16 {%0,%1,%2,%3}, [%4];"
                    : "=r"(af[0]), "=r"(af[1]), "=r"(af[2]), "=r"(af[3]) : "r"(ad));
            }
            #pragma unroll
            for (int nt = 0; nt < 4; nt++) {
                uint32_t bd = sB_base + b * BUFB + boff0 + nt * (8 * ROWP * 2) + kb;
                asm volatile("ldmatrix.sync.aligned.m8n8.x2.shared.b16 {%0,%1}, [%2];"
                    : "=r"(bfr[nt][0]), "=r"(bfr[nt][1]) : "r"(bd));
            }
            #pragma unroll
            for (int nt = 0; nt < 4; nt++)
                asm volatile("mma.sync.aligned.m16n8k16.row.col.f32.bf16.bf16.f32 "
                    "{%0,%1,%2,%3}, {%4,%5,%6,%7}, {%8,%9}, {%0,%1,%2,%3};"
                    : "+f"(acc[nt][0]), "+f"(acc[nt][1]), "+f"(acc[nt][2]), "+f"(acc[nt][3])
                    : "r"(af[0]), "r"(af[1]), "r"(af[2]), "r"(af[3]),
                      "r"(bfr[nt][0]), "r"(bfr[nt][1]));
        }
        if (more) {
            __syncthreads();
            #pragma unroll
            for (int u = 0; u < 2; u++) {
                int idx = tid + u * 256;
                int row = idx >> 3, c = idx & 7;
                *(uint4*)((char*)&sA[b ^ 1][0][0] + row * (ROWP * 2) + c * 16) = pa[u];
                *(uint4*)((char*)&sB[b ^ 1][0][0] + row * (ROWP * 2) + c * 16) = pb[u];
            }
            __syncthreads();
        }
    }

    int r = m0 + Mw + (lane >> 2);
    #pragma unroll
    for (int nt = 0; nt < 4; nt++) {
        int col = n0 + Nw + nt * 8 + ((lane & 3) << 1);
        float b0v = bias[col], b1v = bias[col + 1];
        float2 o0 = { acc[nt][0] + b0v, acc[nt][1] + b1v };
        float2 o1 = { acc[nt][2] + b0v, acc[nt][3] + b1v };
        *(float2*)&C[(size_t)r * Nld + col] = o0;
        *(float2*)&C[(size_t)(r + 8) * Nld + col] = o1;
    }
}

// ================= pointify =================
__global__ void pointify(const float* __restrict__ proj,
                         const float* __restrict__ rot,
                         const float* __restrict__ trans,
                         const float* __restrict__ head_w,
                         float* __restrict__ kext, float* __restrict__ qext,
                         float* __restrict__ v, float* __restrict__ vpts) {
    int n = blockIdx.x, t = threadIdx.x;   // 256 threads
    __shared__ float Rs[9], ts[3], qg[144], kg[432], hw_s[12];
    const float* prow = proj + (size_t)n * 1152;
    if (t < 9) Rs[t] = rot[n * 9 + t];
    if (t >= 16 && t < 19) ts[t - 16] = trans[n * 3 + (t - 16)];
    if (t >= 32 && t < 44) {
        float w = head_w[t - 32];
        float sp = (w > 20.f) ? w : log1pf(expf(w));
        hw_s[t - 32] = sp * 0.13608276348795434f;   // sqrt(1/54)
    }
    __syncthreads();
    if (t < 48) {
        float x  = prow[576 + t];
        float y  = prow[576 + 48 + t];
        float zc = prow[576 + 96 + t];
        qg[t * 3 + 0] = Rs[0] * x + Rs[1] * y + Rs[2] * zc + ts[0];
        qg[t * 3 + 1] = Rs[3] * x + Rs[4] * y + Rs[5] * zc + ts[1];
        qg[t * 3 + 2] = Rs[6] * x + Rs[7] * y + Rs[8] * zc + ts[2];
    }
    if (t >= 64 && t < 208) {
        int pf = t - 64;
        float x  = prow[720 + pf];
        float y  = prow[720 + 144 + pf];
        float zc = prow[720 + 288 + pf];
        kg[pf * 3 + 0] = Rs[0] * x + Rs[1] * y + Rs[2] * zc + ts[0];
        kg[pf * 3 + 1] = Rs[3] * x + Rs[4] * y + Rs[5] * zc + ts[1];
        kg[pf * 3 + 2] = Rs[6] * x + Rs[7] * y + Rs[8] * zc + ts[2];
    }
    __syncthreads();
    if (t < 192) {
        int hh = t >> 4, d = t & 15;
        kext[((size_t)hh * 512 + n) * 32 + d] = prow[192 + hh * 32 + d];
        v[(size_t)n * 192 + t]                = prow[192 + hh * 32 + 16 + d];
        qext[((size_t)n * 12 + hh) * 32 + d]  = 0.14433756729740643f * prow[t];
    }
    for (int idx = t; idx < 288; idx += 256) {
        int hh = idx / 24, rem = idx % 24;
        vpts[(size_t)n * 288 + idx] = kg[hh * 36 + 12 + rem];
    }
    if (t < 12) {
        int hh = t; float hw = hw_s[hh];
        float Sk = 0.f, Sq = 0.f;
        float* ke = &kext[((size_t)hh * 512 + n) * 32];
        float* qe = &qext[((size_t)n * 12 + hh) * 32];
        #pragma unroll
        for (int u = 0; u < 12; u++) {
            float kvv = kg[hh * 36 + u];  Sk += kvv * kvv;  ke[16 + u] = kvv;
            float qvv = qg[hh * 12 + u];  Sq += qvv * qvv;  qe[16 + u] = hw * qvv;
        }
        ke[28] = -0.5f * hw * Sk; ke[29] = 1.f; ke[30] = 0.f; ke[31] = 0.f;
        qe[28] = 1.f; qe[29] = -0.5f * hw * Sq; qe[30] = 0.f; qe[31] = 0.f;
    }
}

// ================= bproj: 64-row tiles, float4 smem streams =================
__global__ void bproj64(const float* __restrict__ z,
                        const float* __restrict__ Wb,
                        const float* __restrict__ bb,
                        float* __restrict__ bmat) {
    __shared__ float zs[64 * 132];        // [row][132], float4-aligned rows
    __shared__ float Wb_s[12 * 132];      // [h][132] transposed, scaled by c_b
    __shared__ float bb_s[12];
    const float c_b = 0.5773502691896258f;
    int t = threadIdx.x;                    // 256
    size_t r0 = (size_t)blockIdx.x * 64;
    for (int idx = t; idx < 1536; idx += 256) {
        int d = idx / 12, h = idx - d * 12;
        Wb_s[h * 132 + d] = c_b * Wb[idx];
    }
    if (t < 12) bb_s[t] = c_b * bb[t];
    #pragma unroll
    for (int u = 0; u < 8; u++) {
        int idx = t + u * 256;
        int row = idx >> 5, c4 = (idx & 31) << 2;
        float4 vv = *(const float4*)&z[(r0 + row) * 128 + c4];
        *(float4*)&zs[row * 132 + c4] = vv;
    }
    __syncthreads();
    int rg = t >> 2, hg = (t & 3) * 3;
    float acc0 = 0.f, acc1 = 0.f, acc2 = 0.f;
    const float* zrow = &zs[rg * 132];
    const float* w0p = &Wb_s[(hg + 0) * 132];
    const float* w1p = &Wb_s[(hg + 1) * 132];
    const float* w2p = &Wb_s[(hg + 2) * 132];
    #pragma unroll 8
    for (int d4 = 0; d4 < 32; d4++) {
        float4 zv = *(const float4*)&zrow[d4 << 2];
        float4 w0 = *(const float4*)&w0p[d4 << 2];
        float4 w1 = *(const float4*)&w1p[d4 << 2];
        float4 w2 = *(const float4*)&w2p[d4 << 2];
        acc0 += zv.x * w0.x + zv.y * w0.y + zv.z * w0.z + zv.w * w0.w;
        acc1 += zv.x * w1.x + zv.y * w1.y + zv.z * w1.z + zv.w * w1.w;
        acc2 += zv.x * w2.x + zv.y * w2.y + zv.z * w2.z + zv.w * w2.w;
    }
    size_t row = r0 + rg;
    int i = (int)(row >> 9), j = (int)(row & 511);
    bmat[((size_t)i * 12 + hg + 0) * 512 + j] = acc0 + bb_s[hg + 0];
    bmat[((size_t)i * 12 + hg + 1) * 512 + j] = acc1 + bb_s[hg + 1];
    bmat[((size_t)i * 12 + hg + 2) * 512 + j] = acc2 + bb_s[hg + 2];
}

// ================= logits (rank-30) + mask + softmax, 16 rows/block =================
__global__ void logits_softmax(const float* __restrict__ qext,
                               const float* __restrict__ kext,
                               const float* __restrict__ bmat,
                               const float* __restrict__ mask,
                               float* __restrict__ a) {
    int i0 = blockIdx.x * 16, h = blockIdx.y;   // grid (32, 12)
    int t = threadIdx.x;     // 256
    int w = t >> 5, l = t & 31;
    __shared__ __align__(16) float qe[16][32];
    __shared__ __align__(16) float ke[32][65];
    __shared__ __align__(16) float b_s[16][64];
    __shared__ float ms[512], mi_s[16];
    if (t < 128) {
        int r = t >> 3, d4 = (t & 7) << 2;
        *(float4*)&qe[r][d4] = *(const float4*)&qext[((size_t)(i0 + r) * 12 + h) * 32 + d4];
    }
    for (int idx = t; idx < 512; idx += 256) ms[idx] = mask[idx];
    if (t < 16) mi_s[t] = mask[i0 + t];
    float rmax[2] = {-3.4e38f, -3.4e38f};
    for (int jt = 0; jt < 8; jt++) {
        int j0 = jt * 64;
        __syncthreads();
        #pragma unroll
        for (int idx = t; idx < 512; idx += 256) {
            int jr = idx >> 3, d4 = (idx & 7) << 2;
            float4 kv = *(const float4*)&kext[((size_t)h * 512 + j0 + jr) * 32 + d4];
            ke[d4 + 0][jr] = kv.x; ke[d4 + 1][jr] = kv.y;
            ke[d4 + 2][jr] = kv.z; ke[d4 + 3][jr] = kv.w;
        }
        {
            int r = t >> 4, c4 = (t & 15) << 2;
            *(float4*)&b_s[r][c4] =
                *(const float4*)&bmat[((size_t)(i0 + r) * 12 + h) * 512 + j0 + c4];
        }
        __syncthreads();
        float acc[2][2] = {};
        #pragma unroll 5
        for (int d = 0; d < 30; d++) {
            float k0 = ke[d][l], k1 = ke[d][l + 32];
            #pragma unroll
            for (int rr = 0; rr < 2; rr++) {
                float qv = qe[(w << 1) + rr][d];
                acc[rr][0] += qv * k0;
                acc[rr][1] += qv * k1;
            }
        }
        float mj0 = ms[j0 + l], mj1 = ms[j0 + l + 32];
        #pragma unroll
        for (int rr = 0; rr < 2; rr++) {
            int r = (w << 1) + rr;
            float mi = mi_s[r];
            float lg0 = acc[rr][0] + b_s[r][l]      + INF_ * fmaf(mi, mj0, -1.f);
            float lg1 = acc[rr][1] + b_s[r][l + 32] + INF_ * fmaf(mi, mj1, -1.f);
            float* arow = a + ((size_t)(i0 + r) * 12 + h) * 512 + j0;
            arow[l] = lg0;
            arow[l + 32] = lg1;
            rmax[rr] = fmaxf(rmax[rr], fmaxf(lg0, lg1));
        }
    }
    #pragma unroll
    for (int off = 16; off > 0; off >>= 1)
        #pragma unroll
        for (int rr = 0; rr < 2; rr++)
            rmax[rr] = fmaxf(rmax[rr], __shfl_xor_sync(0xffffffffu, rmax[rr], off));
    #pragma unroll
    for (int rr = 0; rr < 2; rr++) {
        float* arow = a + ((size_t)(i0 + (w << 1) + rr) * 12 + h) * 512;
        float mx = rmax[rr];
        float sum = 0.f;
        #pragma unroll
        for (int c = l; c < 512; c += 32) sum += __expf(arow[c] - mx);
        #pragma unroll
        for (int off = 16; off > 0; off >>= 1)
            sum += __shfl_xor_sync(0xffffffffu, sum, off);
        float inv = 1.f / sum;
        #pragma unroll
        for (int c = l; c < 512; c += 32) arow[c] = __expf(arow[c] - mx) * inv;
    }
}

// ================= att_out -> writes bf16 triplets of cols [0,576) into Cint =================
__global__ void att_out(const float* __restrict__ a,
                        const float* __restrict__ v,
                        const float* __restrict__ vpts,
                        const float* __restrict__ rot,
                        const float* __restrict__ trans,
                        __nv_bfloat16* __restrict__ Cint) {
    int i0 = blockIdx.x * 4;
    int t = threadIdx.x;    // 480
    __shared__ float a_s[4][768];
    __shared__ float opts[4][288];
    __shared__ float cvals[4][576];
    __shared__ float Rs[4][9], ts[4][3];
    if (t < 36) Rs[t / 9][t % 9] = rot[(i0 + t / 9) * 9 + t % 9];
    if (t >= 64 && t < 76) {
        int r = (t - 64) / 3, cpt = (t - 64) % 3;
        ts[r][cpt] = trans[(i0 + r) * 3 + cpt];
    }
    float acc[4] = {0.f, 0.f, 0.f, 0.f};
    int h = (t < 192) ? (t >> 4) : ((t - 192) / 24);
    const float* src = (t < 192) ? (v + t) : (vpts + (t - 192));
    int stride = (t < 192) ? 192 : 288;
    for (int j0 = 0; j0 < 512; j0 += 64) {
        for (int idx = t; idx < 3072; idx += 480) {
            int r = idx / 768;
            int rem = idx - r * 768;
            int hh = rem >> 6, jj = rem & 63;
            a_s[r][rem] = a[((size_t)(i0 + r) * 12 + hh) * 512 + j0 + jj];
        }
        __syncthreads();
        const float* sp = src + (size_t)j0 * stride;
        const float* as0 = &a_s[0][h * 64];
        #pragma unroll 4
        for (int jj = 0; jj < 64; jj++) {
            float val = sp[(size_t)jj * stride];
            acc[0] += as0[jj]        * val;
            acc[1] += as0[768 + jj]  * val;
            acc[2] += as0[1536 + jj] * val;
            acc[3] += as0[2304 + jj] * val;
        }
        __syncthreads();
    }
    if (t >= 192) {
        #pragma unroll
        for (int r = 0; r < 4; r++) opts[r][t - 192] = acc[r];
    }
    __syncthreads();
    #pragma unroll
    for (int r = 0; r < 4; r++) {
        if (t < 192) cvals[r][t] = acc[r];
        if (t < 96) {
            int hh = t >> 3, p = t & 7;
            int base = hh * 24 + p * 3;
            float gx = opts[r][base]     - ts[r][0];
            float gy = opts[r][base + 1] - ts[r][1];
            float gz = opts[r][base + 2] - ts[r][2];
            float lx = Rs[r][0] * gx + Rs[r][3] * gy + Rs[r][6] * gz;
            float ly = Rs[r][1] * gx + Rs[r][4] * gy + Rs[r][7] * gz;
            float lz = Rs[r][2] * gx + Rs[r][5] * gy + Rs[r][8] * gz;
            cvals[r][192 + t] = lx;
            cvals[r][288 + t] = ly;
            cvals[r][384 + t] = lz;
            cvals[r][480 + t] = sqrtf(lx * lx + ly * ly + lz * lz + 1e-8f);
        }
    }
    __syncthreads();
    for (int idx = t; idx < 4 * 288; idx += 480) {
        int r = idx / 288, p = idx - r * 288;
        uint32_t* d = (uint32_t*)(Cint + (size_t)(i0 + r) * 6336);
        bf16pair_store(d, p, cvals[r][2 * p], cvals[r][2 * p + 1]);
    }
}

// ================= opair: 2 j-groups x 128 cols -> bf16 triplets cols [576,2112) =================
__global__ void __launch_bounds__(256) opair(const float* __restrict__ a,
                                             const float* __restrict__ z,
                                             __nv_bfloat16* __restrict__ Cint) {
    int i = blockIdx.x;
    int t = threadIdx.x;           // 256
    int jg = t >> 7, c = t & 127;  // j-group, column
    __shared__ __align__(16) float a_s[2][768];
    __shared__ float red[12][128];
    float acc[12] = {};
    for (int jt = 0; jt < 4; jt++) {
        int j0 = jg * 256 + jt * 64;
        for (int idx = c; idx < 768; idx += 128) {
            int hh = idx >> 6, jj = idx & 63;
            a_s[jg][idx] = a[((size_t)i * 12 + hh) * 512 + j0 + jj];
        }
        __syncthreads();
        const float* zp = z + ((size_t)i * 512 + j0) * 128 + c;
        #pragma unroll
        for (int jj4 = 0; jj4 < 16; jj4++) {
            int jj = jj4 * 4;
            float z0 = zp[(size_t)(jj + 0) * 128];
            float z1 = zp[(size_t)(jj + 1) * 128];
            float z2 = zp[(size_t)(jj + 2) * 128];
            float z3 = zp[(size_t)(jj + 3) * 128];
            #pragma unroll
            for (int hh = 0; hh < 12; hh++) {
                float4 av = *(const float4*)&a_s[jg][hh * 64 + jj];
                acc[hh] += av.x * z0 + av.y * z1 + av.z * z2 + av.w * z3;
            }
        }
        __syncthreads();
    }
    if (jg == 1) {
        #pragma unroll
        for (int hh = 0; hh < 12; hh++) red[hh][c] = acc[hh];
    }
    __syncthreads();
    if (jg == 0) {
        uint32_t* d = (uint32_t*)(Cint + (size_t)i * 6336);
        #pragma unroll
        for (int hh = 0; hh < 12; hh++) {
            float tot = acc[hh] + red[hh][c];
            float other = __shfl_xor_sync(0xffffffffu, tot, 1);
            if (!(c & 1)) {
                int p = 288 + hh * 64 + (c >> 1);
                bf16pair_store(d, p, tot, other);
            }
        }
    }
}

// ================= launch =================
extern "C" void kernel_launch(void* const* d_in, const int* in_sizes, int n_in,
                              void* d_out, int out_size) {
    const float* s      = (const float*)d_in[0];
    const float* z      = (const float*)d_in[1];
    const float* rot    = (const float*)d_in[2];
    const float* trans  = (const float*)d_in[3];
    const float* mask   = (const float*)d_in[4];
    const float* Wq     = (const float*)d_in[5];
    const float* bq     = (const float*)d_in[6];
    const float* Wkv    = (const float*)d_in[7];
    const float* bkv    = (const float*)d_in[8];
    const float* Wqp    = (const float*)d_in[9];
    const float* bqp    = (const float*)d_in[10];
    const float* Wkvp   = (const float*)d_in[11];
    const float* bkvp   = (const float*)d_in[12];
    const float* Wb     = (const float*)d_in[13];
    const float* bb     = (const float*)d_in[14];
    const float* head_w = (const float*)d_in[15];
    const float* Wout   = (const float*)d_in[16];
    const float* bout   = (const float*)d_in[17];
    float* out = (float*)d_out;

    float* base = nullptr;
    cudaGetSymbolAddress((void**)&base, g_scratch);
    float* proj  = base + OFF_PROJ;
    float* kext  = base + OFF_KEXT;
    float* qext  = base + OFF_QEXT;
    float* v     = base + OFF_V;
    float* vpts  = base + OFF_VPTS;
    float* bmat  = base + OFF_B;
    float* amat  = base + OFF_A;
    __nv_bfloat16* Aint  = (__nv_bfloat16*)(base + OFF_AINT);
    __nv_bfloat16* WintP = (__nv_bfloat16*)(base + OFF_WINTP);
    __nv_bfloat16* Cint  = (__nv_bfloat16*)(base + OFF_CINT);
    __nv_bfloat16* WintO = (__nv_bfloat16*)(base + OFF_WINTO);
    float* biasA = base + OFF_BIASA;

    prep_all<<<7813, 256>>>(s, Wq, Wkv, Wqp, Wkvp, Wout, bq, bkv, bqp, bkvp,
                            Aint, WintP, WintO, biasA);

    // fused projection GEMM: [512,1152] = s @ [Wq|Wkv|Wqp|Wkvp]
    mma_gemm<<<dim3(18, 8), 256>>>(Aint, WintP, biasA, proj, 3072, 1152);

    pointify<<<512, 256>>>(proj, rot, trans, head_w, kext, qext, v, vpts);
    bproj64<<<4096, 256>>>(z, Wb, bb, bmat);
    logits_softmax<<<dim3(32, 12), 256>>>(qext, kext, bmat, mask, amat);
    att_out<<<128, 480>>>(amat, v, vpts, rot, trans, Cint);
    opair<<<512, 256>>>(amat, z, Cint);

    // output GEMM: [512,1024] = cat @ Wout (cat already split into Cint)
    mma_gemm<<<dim3(16, 8), 256>>>(Cint, WintO, bout, out, 6336, 1024);
}

// round 12
// speedup vs baseline: 2.2740x; 1.0484x over previous
#include <cuda_runtime.h>
#include <cuda_bf16.h>
#include <math.h>
#include <stdint.h>

#define INF_ 100000.0f

// ================= scratch (floats) =================
static constexpr size_t OFF_PROJ  = 0;                                 // 512*1152
static constexpr size_t OFF_KEXT  = OFF_PROJ  + (size_t)512*1152;      // 12*512*32
static constexpr size_t OFF_QEXT  = OFF_KEXT  + (size_t)12*512*32;     // 512*12*32
static constexpr size_t OFF_V     = OFF_QEXT  + (size_t)512*12*32;     // 512*192
static constexpr size_t OFF_VPTS  = OFF_V     + (size_t)512*192;       // 512*288
static constexpr size_t OFF_B     = OFF_VPTS  + (size_t)512*288;       // 512*12*512
static constexpr size_t OFF_A     = OFF_B     + (size_t)512*12*512;    // 512*12*512
static constexpr size_t OFF_AINT  = OFF_A     + (size_t)512*12*512;    // bf16 512*3072
static constexpr size_t OFF_WINTP = OFF_AINT  + (size_t)512*3072/2;    // bf16 1152*3072
static constexpr size_t OFF_CINT  = OFF_WINTP + (size_t)1152*3072/2;   // bf16 512*6336
static constexpr size_t OFF_WINTO = OFF_CINT  + (size_t)512*6336/2;    // bf16 1024*6336
static constexpr size_t OFF_BIASA = OFF_WINTO + (size_t)1024*6336/2;   // 1152
static constexpr size_t SCRATCH_TOTAL = OFF_BIASA + 1152;

__device__ __align__(256) float g_scratch[SCRATCH_TOTAL];

__device__ __forceinline__ uint32_t smem_u32(const void* p) {
    uint32_t a;
    asm("{ .reg .u64 t; cvta.to.shared.u64 t, %1; cvt.u32.u64 %0, t; }" : "=r"(a) : "l"(p));
    return a;
}

// write one fp32 pair as the 3-u32 interleaved hi/lo pattern (A-side: [hi,lo][hi,hi][lo,hi])
__device__ __forceinline__ void bf16pair_store(uint32_t* d, int p, float a0, float a1) {
    __nv_bfloat16 h0 = __float2bfloat16(a0);
    __nv_bfloat16 l0 = __float2bfloat16(a0 - __bfloat162float(h0));
    __nv_bfloat16 h1 = __float2bfloat16(a1);
    __nv_bfloat16 l1 = __float2bfloat16(a1 - __bfloat162float(h1));
    uint32_t uh0 = __bfloat16_as_ushort(h0), ul0 = __bfloat16_as_ushort(l0);
    uint32_t uh1 = __bfloat16_as_ushort(h1), ul1 = __bfloat16_as_ushort(l1);
    d[3 * p + 0] = uh0 | (ul0 << 16);
    d[3 * p + 1] = uh0 | (uh1 << 16);
    d[3 * p + 2] = ul1 | (uh1 << 16);
}

// ================= prep_all =================
__device__ __forceinline__ void wsplit_body(const float* __restrict__ W,
                                            __nv_bfloat16* __restrict__ dst,
                                            int N, int Kp, int rowoff, int kp, int n) {
    if (n >= N) return;
    float a0 = W[(size_t)(2 * kp) * N + n];
    float a1 = W[(size_t)(2 * kp + 1) * N + n];
    __nv_bfloat16 h0 = __float2bfloat16(a0);
    __nv_bfloat16 l0 = __float2bfloat16(a0 - __bfloat162float(h0));
    __nv_bfloat16 h1 = __float2bfloat16(a1);
    __nv_bfloat16 l1 = __float2bfloat16(a1 - __bfloat162float(h1));
    uint32_t uh0 = __bfloat16_as_ushort(h0), ul0 = __bfloat16_as_ushort(l0);
    uint32_t uh1 = __bfloat16_as_ushort(h1), ul1 = __bfloat16_as_ushort(l1);
    uint32_t* d = (uint32_t*)(dst + (size_t)(rowoff + n) * Kp) + 3 * kp;
    d[0] = uh0 | (uh0 << 16);   // W-side: [hi,hi][lo,hi][hi,lo]
    d[1] = ul0 | (uh1 << 16);
    d[2] = uh1 | (ul1 << 16);
}

__global__ void prep_all(const float* __restrict__ s,
                         const float* __restrict__ Wq,  const float* __restrict__ Wkv,
                         const float* __restrict__ Wqp, const float* __restrict__ Wkvp,
                         const float* __restrict__ Wout,
                         const float* __restrict__ bq,  const float* __restrict__ bkv,
                         const float* __restrict__ bqp, const float* __restrict__ bkvp,
                         __nv_bfloat16* __restrict__ Aint,
                         __nv_bfloat16* __restrict__ WintP,
                         __nv_bfloat16* __restrict__ WintO,
                         float* __restrict__ biasA) {
    int bid = blockIdx.x, t = threadIdx.x;     // 256 threads
    if (bid < 512) {
        const float* sr = s + (size_t)bid * 1024;
        uint32_t* d = (uint32_t*)(Aint + (size_t)bid * 3072);
        #pragma unroll
        for (int u = 0; u < 2; u++) {
            int p = t + u * 256;
            float a0 = sr[2 * p], a1 = sr[2 * p + 1];
            __nv_bfloat16 h0 = __float2bfloat16(a0);
            __nv_bfloat16 l0 = __float2bfloat16(a0 - __bfloat162float(h0));
            __nv_bfloat16 h1 = __float2bfloat16(a1);
            __nv_bfloat16 l1 = __float2bfloat16(a1 - __bfloat162float(h1));
            uint32_t uh0 = __bfloat16_as_ushort(h0), ul0 = __bfloat16_as_ushort(l0);
            uint32_t uh1 = __bfloat16_as_ushort(h1), ul1 = __bfloat16_as_ushort(l1);
            d[3 * p + 0] = uh0 | (ul0 << 16);
            d[3 * p + 1] = uh0 | (uh1 << 16);
            d[3 * p + 2] = ul1 | (uh1 << 16);
        }
    } else if (bid < 1024) {
        wsplit_body(Wq, WintP, 192, 3072, 0, bid - 512, t);
    } else if (bid < 2048) {
        int local = bid - 1024;
        wsplit_body(Wkv, WintP, 384, 3072, 192, local >> 1, ((local & 1) << 8) + t);
    } else if (bid < 2560) {
        wsplit_body(Wqp, WintP, 144, 3072, 576, bid - 2048, t);
    } else if (bid < 3584) {
        int local = bid - 2560;
        wsplit_body(Wkvp, WintP, 432, 3072, 720, local >> 1, ((local & 1) << 8) + t);
    } else if (bid < 7808) {
        int local = bid - 3584;
        wsplit_body(Wout, WintO, 1024, 6336, 0, local >> 2, ((local & 3) << 8) + t);
    } else {
        int idx = (bid - 7808) * 256 + t;
        if (idx < 1152) {
            float v;
            if (idx < 192) v = bq[idx];
            else if (idx < 576) v = bkv[idx - 192];
            else if (idx < 720) v = bqp[idx - 576];
            else v = bkvp[idx - 720];
            biasA[idx] = v;
        }
    }
}

// ================= warp-MMA bf16 GEMM: 256 thr, 64x64 tile, 8 warps (16x32 each) =================
#define ROWP 72
#define BUFB (64 * ROWP * 2)

__global__ void __launch_bounds__(256) mma_gemm(const __nv_bfloat16* __restrict__ A,
                                                const __nv_bfloat16* __restrict__ B,
                                                const float* __restrict__ bias,
                                                float* __restrict__ C,
                                                int Kp, int Nld) {
    __shared__ __align__(16) __nv_bfloat16 sA[2][64][ROWP];
    __shared__ __align__(16) __nv_bfloat16 sB[2][64][ROWP];
    int tid = threadIdx.x, wid = tid >> 5, lane = tid & 31;
    int m0 = blockIdx.y * 64, n0 = blockIdx.x * 64;
    int Mw = (wid >> 1) * 16, Nw = (wid & 1) * 32;

    uint32_t sA_base = smem_u32(&sA[0][0][0]);
    uint32_t sB_base = smem_u32(&sB[0][0][0]);
    uint32_t aoff0 = ((uint32_t)((Mw + (lane & 15)) * ROWP + ((lane >> 4) << 3))) << 1;
    uint32_t boff0 = ((uint32_t)((Nw + (lane & 7)) * ROWP + (lane & 8))) << 1;

    const char* Abase = (const char*)A;
    const char* Bbase = (const char*)B;
    int ntiles = Kp >> 6;

    #pragma unroll
    for (int u = 0; u < 2; u++) {
        int idx = tid + u * 256;
        int row = idx >> 3, c = idx & 7;
        *(uint4*)((char*)&sA[0][0][0] + row * (ROWP * 2) + c * 16) =
            *(const uint4*)(Abase + ((size_t)(m0 + row) * Kp + c * 8) * 2);
        *(uint4*)((char*)&sB[0][0][0] + row * (ROWP * 2) + c * 16) =
            *(const uint4*)(Bbase + ((size_t)(n0 + row) * Kp + c * 8) * 2);
    }
    __syncthreads();

    float acc[4][4] = {};
    for (int t = 0; t < ntiles; t++) {
        int b = t & 1;
        uint4 pa[2], pb[2];
        bool more = (t + 1) < ntiles;
        if (more) {
            #pragma unroll
            for (int u = 0; u < 2; u++) {
                int idx = tid + u * 256;
                int row = idx >> 3, c = idx & 7;
                pa[u] = *(const uint4*)(Abase + ((size_t)(m0 + row) * Kp + (t + 1) * 64 + c * 8) * 2);
                pb[u] = *(const uint4*)(Bbase + ((size_t)(n0 + row) * Kp + (t + 1) * 64 + c * 8) * 2);
            }
        }
        #pragma unroll
        for (int ks = 0; ks < 4; ks++) {
            uint32_t kb = (uint32_t)ks << 5;
            uint32_t af[4], bfr[4][2];
            {
                uint32_t ad = sA_base + b * BUFB + aoff0 + kb;
                asm volatile("ldmatrix.sync.aligned.m8n8.x4.shared.b16 {%0,%1,%2,%3}, [%4];"
                    : "=r"(af[0]), "=r"(af[1]), "=r"(af[2]), "=r"(af[3]) : "r"(ad));
            }
            #pragma unroll
            for (int nt = 0; nt < 4; nt++) {
                uint32_t bd = sB_base + b * BUFB + boff0 + nt * (8 * ROWP * 2) + kb;
                asm volatile("ldmatrix.sync.aligned.m8n8.x2.shared.b16 {%0,%1}, [%2];"
                    : "=r"(bfr[nt][0]), "=r"(bfr[nt][1]) : "r"(bd));
            }
            #pragma unroll
            for (int nt = 0; nt < 4; nt++)
                asm volatile("mma.sync.aligned.m16n8k16.row.col.f32.bf16.bf16.f32 "
                    "{%0,%1,%2,%3}, {%4,%5,%6,%7}, {%8,%9}, {%0,%1,%2,%3};"
                    : "+f"(acc[nt][0]), "+f"(acc[nt][1]), "+f"(acc[nt][2]), "+f"(acc[nt][3])
                    : "r"(af[0]), "r"(af[1]), "r"(af[2]), "r"(af[3]),
                      "r"(bfr[nt][0]), "r"(bfr[nt][1]));
        }
        if (more) {
            __syncthreads();
            #pragma unroll
            for (int u = 0; u < 2; u++) {
                int idx = tid + u * 256;
                int row = idx >> 3, c = idx & 7;
                *(uint4*)((char*)&sA[b ^ 1][0][0] + row * (ROWP * 2) + c * 16) = pa[u];
                *(uint4*)((char*)&sB[b ^ 1][0][0] + row * (ROWP * 2) + c * 16) = pb[u];
            }
            __syncthreads();
        }
    }

    int r = m0 + Mw + (lane >> 2);
    #pragma unroll
    for (int nt = 0; nt < 4; nt++) {
        int col = n0 + Nw + nt * 8 + ((lane & 3) << 1);
        float b0v = bias[col], b1v = bias[col + 1];
        float2 o0 = { acc[nt][0] + b0v, acc[nt][1] + b1v };
        float2 o1 = { acc[nt][2] + b0v, acc[nt][3] + b1v };
        *(float2*)&C[(size_t)r * Nld + col] = o0;
        *(float2*)&C[(size_t)(r + 8) * Nld + col] = o1;
    }
}

// ================= pointify =================
__global__ void pointify(const float* __restrict__ proj,
                         const float* __restrict__ rot,
                         const float* __restrict__ trans,
                         const float* __restrict__ head_w,
                         float* __restrict__ kext, float* __restrict__ qext,
                         float* __restrict__ v, float* __restrict__ vpts) {
    int n = blockIdx.x, t = threadIdx.x;   // 256 threads
    __shared__ float Rs[9], ts[3], qg[144], kg[432], hw_s[12];
    const float* prow = proj + (size_t)n * 1152;
    if (t < 9) Rs[t] = rot[n * 9 + t];
    if (t >= 16 && t < 19) ts[t - 16] = trans[n * 3 + (t - 16)];
    if (t >= 32 && t < 44) {
        float w = head_w[t - 32];
        float sp = (w > 20.f) ? w : log1pf(expf(w));
        hw_s[t - 32] = sp * 0.13608276348795434f;   // sqrt(1/54)
    }
    __syncthreads();
    if (t < 48) {
        float x  = prow[576 + t];
        float y  = prow[576 + 48 + t];
        float zc = prow[576 + 96 + t];
        qg[t * 3 + 0] = Rs[0] * x + Rs[1] * y + Rs[2] * zc + ts[0];
        qg[t * 3 + 1] = Rs[3] * x + Rs[4] * y + Rs[5] * zc + ts[1];
        qg[t * 3 + 2] = Rs[6] * x + Rs[7] * y + Rs[8] * zc + ts[2];
    }
    if (t >= 64 && t < 208) {
        int pf = t - 64;
        float x  = prow[720 + pf];
        float y  = prow[720 + 144 + pf];
        float zc = prow[720 + 288 + pf];
        kg[pf * 3 + 0] = Rs[0] * x + Rs[1] * y + Rs[2] * zc + ts[0];
        kg[pf * 3 + 1] = Rs[3] * x + Rs[4] * y + Rs[5] * zc + ts[1];
        kg[pf * 3 + 2] = Rs[6] * x + Rs[7] * y + Rs[8] * zc + ts[2];
    }
    __syncthreads();
    if (t < 192) {
        int hh = t >> 4, d = t & 15;
        kext[((size_t)hh * 512 + n) * 32 + d] = prow[192 + hh * 32 + d];
        v[(size_t)n * 192 + t]                = prow[192 + hh * 32 + 16 + d];
        qext[((size_t)n * 12 + hh) * 32 + d]  = 0.14433756729740643f * prow[t];
    }
    for (int idx = t; idx < 288; idx += 256) {
        int hh = idx / 24, rem = idx % 24;
        vpts[(size_t)n * 288 + idx] = kg[hh * 36 + 12 + rem];
    }
    if (t < 12) {
        int hh = t; float hw = hw_s[hh];
        float Sk = 0.f, Sq = 0.f;
        float* ke = &kext[((size_t)hh * 512 + n) * 32];
        float* qe = &qext[((size_t)n * 12 + hh) * 32];
        #pragma unroll
        for (int u = 0; u < 12; u++) {
            float kvv = kg[hh * 36 + u];  Sk += kvv * kvv;  ke[16 + u] = kvv;
            float qvv = qg[hh * 12 + u];  Sq += qvv * qvv;  qe[16 + u] = hw * qvv;
        }
        ke[28] = -0.5f * hw * Sk; ke[29] = 1.f; ke[30] = 0.f; ke[31] = 0.f;
        qe[28] = 1.f; qe[29] = -0.5f * hw * Sq; qe[30] = 0.f; qe[31] = 0.f;
    }
}

// ================= bproj: 64-row tiles; lanes = distinct rows, Wb broadcast =================
__global__ void bproj64(const float* __restrict__ z,
                        const float* __restrict__ Wb,
                        const float* __restrict__ bb,
                        float* __restrict__ bmat) {
    __shared__ float zs[64 * 132];        // [row][132], float4-aligned rows
    __shared__ float Wb_s[12 * 132];      // [h][132] transposed, scaled by c_b
    __shared__ float bb_s[12];
    const float c_b = 0.5773502691896258f;
    int t = threadIdx.x;                    // 256
    size_t r0 = (size_t)blockIdx.x * 64;
    for (int idx = t; idx < 1536; idx += 256) {
        int d = idx / 12, h = idx - d * 12;
        Wb_s[h * 132 + d] = c_b * Wb[idx];
    }
    if (t < 12) bb_s[t] = c_b * bb[t];
    #pragma unroll
    for (int u = 0; u < 8; u++) {
        int idx = t + u * 256;
        int row = idx >> 5, c4 = (idx & 31) << 2;
        float4 vv = *(const float4*)&z[(r0 + row) * 128 + c4];
        *(float4*)&zs[row * 132 + c4] = vv;
    }
    __syncthreads();
    // lanes 0..31 = 32 DISTINCT rows (no z duplication); whole warp shares the
    // same Wb address (true broadcast, N=1).
    int rg = t & 63, hg = (t >> 6) * 3;
    float acc0 = 0.f, acc1 = 0.f, acc2 = 0.f;
    const float* zrow = &zs[rg * 132];
    const float* w0p = &Wb_s[(hg + 0) * 132];
    const float* w1p = &Wb_s[(hg + 1) * 132];
    const float* w2p = &Wb_s[(hg + 2) * 132];
    #pragma unroll 8
    for (int d4 = 0; d4 < 32; d4++) {
        float4 zv = *(const float4*)&zrow[d4 << 2];
        float4 w0 = *(const float4*)&w0p[d4 << 2];
        float4 w1 = *(const float4*)&w1p[d4 << 2];
        float4 w2 = *(const float4*)&w2p[d4 << 2];
        acc0 += zv.x * w0.x + zv.y * w0.y + zv.z * w0.z + zv.w * w0.w;
        acc1 += zv.x * w1.x + zv.y * w1.y + zv.z * w1.z + zv.w * w1.w;
        acc2 += zv.x * w2.x + zv.y * w2.y + zv.z * w2.z + zv.w * w2.w;
    }
    size_t row = r0 + rg;
    int i = (int)(row >> 9), j = (int)(row & 511);
    bmat[((size_t)i * 12 + hg + 0) * 512 + j] = acc0 + bb_s[hg + 0];
    bmat[((size_t)i * 12 + hg + 1) * 512 + j] = acc1 + bb_s[hg + 1];
    bmat[((size_t)i * 12 + hg + 2) * 512 + j] = acc2 + bb_s[hg + 2];
}

// ================= logits (rank-30) + mask + softmax, 16 rows/block =================
__global__ void logits_softmax(const float* __restrict__ qext,
                               const float* __restrict__ kext,
                               const float* __restrict__ bmat,
                               const float* __restrict__ mask,
                               float* __restrict__ a) {
    int i0 = blockIdx.x * 16, h = blockIdx.y;   // grid (32, 12)
    int t = threadIdx.x;     // 256
    int w = t >> 5, l = t & 31;
    __shared__ __align__(16) float qe[16][32];
    __shared__ __align__(16) float ke[32][65];
    __shared__ __align__(16) float b_s[16][64];
    __shared__ float ms[512], mi_s[16];
    if (t < 128) {
        int r = t >> 3, d4 = (t & 7) << 2;
        *(float4*)&qe[r][d4] = *(const float4*)&qext[((size_t)(i0 + r) * 12 + h) * 32 + d4];
    }
    for (int idx = t; idx < 512; idx += 256) ms[idx] = mask[idx];
    if (t < 16) mi_s[t] = mask[i0 + t];
    float rmax[2] = {-3.4e38f, -3.4e38f};
    for (int jt = 0; jt < 8; jt++) {
        int j0 = jt * 64;
        __syncthreads();
        #pragma unroll
        for (int idx = t; idx < 512; idx += 256) {
            int jr = idx >> 3, d4 = (idx & 7) << 2;
            float4 kv = *(const float4*)&kext[((size_t)h * 512 + j0 + jr) * 32 + d4];
            ke[d4 + 0][jr] = kv.x; ke[d4 + 1][jr] = kv.y;
            ke[d4 + 2][jr] = kv.z; ke[d4 + 3][jr] = kv.w;
        }
        {
            int r = t >> 4, c4 = (t & 15) << 2;
            *(float4*)&b_s[r][c4] =
                *(const float4*)&bmat[((size_t)(i0 + r) * 12 + h) * 512 + j0 + c4];
        }
        __syncthreads();
        float acc[2][2] = {};
        #pragma unroll 5
        for (int d = 0; d < 30; d++) {
            float k0 = ke[d][l], k1 = ke[d][l + 32];
            #pragma unroll
            for (int rr = 0; rr < 2; rr++) {
                float qv = qe[(w << 1) + rr][d];
                acc[rr][0] += qv * k0;
                acc[rr][1] += qv * k1;
            }
        }
        float mj0 = ms[j0 + l], mj1 = ms[j0 + l + 32];
        #pragma unroll
        for (int rr = 0; rr < 2; rr++) {
            int r = (w << 1) + rr;
            float mi = mi_s[r];
            float lg0 = acc[rr][0] + b_s[r][l]      + INF_ * fmaf(mi, mj0, -1.f);
            float lg1 = acc[rr][1] + b_s[r][l + 32] + INF_ * fmaf(mi, mj1, -1.f);
            float* arow = a + ((size_t)(i0 + r) * 12 + h) * 512 + j0;
            arow[l] = lg0;
            arow[l + 32] = lg1;
            rmax[rr] = fmaxf(rmax[rr], fmaxf(lg0, lg1));
        }
    }
    #pragma unroll
    for (int off = 16; off > 0; off >>= 1)
        #pragma unroll
        for (int rr = 0; rr < 2; rr++)
            rmax[rr] = fmaxf(rmax[rr], __shfl_xor_sync(0xffffffffu, rmax[rr], off));
    #pragma unroll
    for (int rr = 0; rr < 2; rr++) {
        float* arow = a + ((size_t)(i0 + (w << 1) + rr) * 12 + h) * 512;
        float mx = rmax[rr];
        float sum = 0.f;
        #pragma unroll
        for (int c = l; c < 512; c += 32) sum += __expf(arow[c] - mx);
        #pragma unroll
        for (int off = 16; off > 0; off >>= 1)
            sum += __shfl_xor_sync(0xffffffffu, sum, off);
        float inv = 1.f / sum;
        #pragma unroll
        for (int c = l; c < 512; c += 32) arow[c] = __expf(arow[c] - mx) * inv;
    }
}

// ================= att_out -> writes bf16 triplets of cols [0,576) into Cint =================
__global__ void att_out(const float* __restrict__ a,
                        const float* __restrict__ v,
                        const float* __restrict__ vpts,
                        const float* __restrict__ rot,
                        const float* __restrict__ trans,
                        __nv_bfloat16* __restrict__ Cint) {
    int i0 = blockIdx.x * 4;
    int t = threadIdx.x;    // 480
    __shared__ float a_s[4][768];
    __shared__ float opts[4][288];
    __shared__ float cvals[4][576];
    __shared__ float Rs[4][9], ts[4][3];
    if (t < 36) Rs[t / 9][t % 9] = rot[(i0 + t / 9) * 9 + t % 9];
    if (t >= 64 && t < 76) {
        int r = (t - 64) / 3, cpt = (t - 64) % 3;
        ts[r][cpt] = trans[(i0 + r) * 3 + cpt];
    }
    float acc[4] = {0.f, 0.f, 0.f, 0.f};
    int h = (t < 192) ? (t >> 4) : ((t - 192) / 24);
    const float* src = (t < 192) ? (v + t) : (vpts + (t - 192));
    int stride = (t < 192) ? 192 : 288;
    for (int j0 = 0; j0 < 512; j0 += 64) {
        for (int idx = t; idx < 3072; idx += 480) {
            int r = idx / 768;
            int rem = idx - r * 768;
            int hh = rem >> 6, jj = rem & 63;
            a_s[r][rem] = a[((size_t)(i0 + r) * 12 + hh) * 512 + j0 + jj];
        }
        __syncthreads();
        const float* sp = src + (size_t)j0 * stride;
        const float* as0 = &a_s[0][h * 64];
        #pragma unroll 4
        for (int jj = 0; jj < 64; jj++) {
            float val = sp[(size_t)jj * stride];
            acc[0] += as0[jj]        * val;
            acc[1] += as0[768 + jj]  * val;
            acc[2] += as0[1536 + jj] * val;
            acc[3] += as0[2304 + jj] * val;
        }
        __syncthreads();
    }
    if (t >= 192) {
        #pragma unroll
        for (int r = 0; r < 4; r++) opts[r][t - 192] = acc[r];
    }
    __syncthreads();
    #pragma unroll
    for (int r = 0; r < 4; r++) {
        if (t < 192) cvals[r][t] = acc[r];
        if (t < 96) {
            int hh = t >> 3, p = t & 7;
            int base = hh * 24 + p * 3;
            float gx = opts[r][base]     - ts[r][0];
            float gy = opts[r][base + 1] - ts[r][1];
            float gz = opts[r][base + 2] - ts[r][2];
            float lx = Rs[r][0] * gx + Rs[r][3] * gy + Rs[r][6] * gz;
            float ly = Rs[r][1] * gx + Rs[r][4] * gy + Rs[r][7] * gz;
            float lz = Rs[r][2] * gx + Rs[r][5] * gy + Rs[r][8] * gz;
            cvals[r][192 + t] = lx;
            cvals[r][288 + t] = ly;
            cvals[r][384 + t] = lz;
            cvals[r][480 + t] = sqrtf(lx * lx + ly * ly + lz * lz + 1e-8f);
        }
    }
    __syncthreads();
    for (int idx = t; idx < 4 * 288; idx += 480) {
        int r = idx / 288, p = idx - r * 288;
        uint32_t* d = (uint32_t*)(Cint + (size_t)(i0 + r) * 6336);
        bf16pair_store(d, p, cvals[r][2 * p], cvals[r][2 * p + 1]);
    }
}

// ================= opair: 2 j-groups x 128 cols -> bf16 triplets cols [576,2112) =================
__global__ void __launch_bounds__(256) opair(const float* __restrict__ a,
                                             const float* __restrict__ z,
                                             __nv_bfloat16* __restrict__ Cint) {
    int i = blockIdx.x;
    int t = threadIdx.x;           // 256
    int jg = t >> 7, c = t & 127;  // j-group, column
    __shared__ __align__(16) float a_s[2][768];
    __shared__ float red[12][128];
    float acc[12] = {};
    for (int jt = 0; jt < 4; jt++) {
        int j0 = jg * 256 + jt * 64;
        for (int idx = c; idx < 768; idx += 128) {
            int hh = idx >> 6, jj = idx & 63;
            a_s[jg][idx] = a[((size_t)i * 12 + hh) * 512 + j0 + jj];
        }
        __syncthreads();
        const float* zp = z + ((size_t)i * 512 + j0) * 128 + c;
        #pragma unroll
        for (int jj4 = 0; jj4 < 16; jj4++) {
            int jj = jj4 * 4;
            float z0 = zp[(size_t)(jj + 0) * 128];
            float z1 = zp[(size_t)(jj + 1) * 128];
            float z2 = zp[(size_t)(jj + 2) * 128];
            float z3 = zp[(size_t)(jj + 3) * 128];
            #pragma unroll
            for (int hh = 0; hh < 12; hh++) {
                float4 av = *(const float4*)&a_s[jg][hh * 64 + jj];
                acc[hh] += av.x * z0 + av.y * z1 + av.z * z2 + av.w * z3;
            }
        }
        __syncthreads();
    }
    if (jg == 1) {
        #pragma unroll
        for (int hh = 0; hh < 12; hh++) red[hh][c] = acc[hh];
    }
    __syncthreads();
    if (jg == 0) {
        uint32_t* d = (uint32_t*)(Cint + (size_t)i * 6336);
        #pragma unroll
        for (int hh = 0; hh < 12; hh++) {
            float tot = acc[hh] + red[hh][c];
            float other = __shfl_xor_sync(0xffffffffu, tot, 1);
            if (!(c & 1)) {
                int p = 288 + hh * 64 + (c >> 1);
                bf16pair_store(d, p, tot, other);
            }
        }
    }
}

// ================= launch =================
extern "C" void kernel_launch(void* const* d_in, const int* in_sizes, int n_in,
                              void* d_out, int out_size) {
    const float* s      = (const float*)d_in[0];
    const float* z      = (const float*)d_in[1];
    const float* rot    = (const float*)d_in[2];
    const float* trans  = (const float*)d_in[3];
    const float* mask   = (const float*)d_in[4];
    const float* Wq     = (const float*)d_in[5];
    const float* bq     = (const float*)d_in[6];
    const float* Wkv    = (const float*)d_in[7];
    const float* bkv    = (const float*)d_in[8];
    const float* Wqp    = (const float*)d_in[9];
    const float* bqp    = (const float*)d_in[10];
    const float* Wkvp   = (const float*)d_in[11];
    const float* bkvp   = (const float*)d_in[12];
    const float* Wb     = (const float*)d_in[13];
    const float* bb     = (const float*)d_in[14];
    const float* head_w = (const float*)d_in[15];
    const float* Wout   = (const float*)d_in[16];
    const float* bout   = (const float*)d_in[17];
    float* out = (float*)d_out;

    float* base = nullptr;
    cudaGetSymbolAddress((void**)&base, g_scratch);
    float* proj  = base + OFF_PROJ;
    float* kext  = base + OFF_KEXT;
    float* qext  = base + OFF_QEXT;
    float* v     = base + OFF_V;
    float* vpts  = base + OFF_VPTS;
    float* bmat  = base + OFF_B;
    float* amat  = base + OFF_A;
    __nv_bfloat16* Aint  = (__nv_bfloat16*)(base + OFF_AINT);
    __nv_bfloat16* WintP = (__nv_bfloat16*)(base + OFF_WINTP);
    __nv_bfloat16* Cint  = (__nv_bfloat16*)(base + OFF_CINT);
    __nv_bfloat16* WintO = (__nv_bfloat16*)(base + OFF_WINTO);
    float* biasA = base + OFF_BIASA;

    prep_all<<<7813, 256>>>(s, Wq, Wkv, Wqp, Wkvp, Wout, bq, bkv, bqp, bkvp,
                            Aint, WintP, WintO, biasA);

    // fused projection GEMM: [512,1152] = s @ [Wq|Wkv|Wqp|Wkvp]
    mma_gemm<<<dim3(18, 8), 256>>>(Aint, WintP, biasA, proj, 3072, 1152);

    pointify<<<512, 256>>>(proj, rot, trans, head_w, kext, qext, v, vpts);
    bproj64<<<4096, 256>>>(z, Wb, bb, bmat);
    logits_softmax<<<dim3(32, 12), 256>>>(qext, kext, bmat, mask, amat);
    att_out<<<128, 480>>>(amat, v, vpts, rot, trans, Cint);
    opair<<<512, 256>>>(amat, z, Cint);

    // output GEMM: [512,1024] = cat @ Wout (cat already split into Cint)
    mma_gemm<<<dim3(16, 8), 256>>>(Cint, WintO, bout, out, 6336, 1024);
}